// round 11
// baseline (speedup 1.0000x reference)
#include <cuda_runtime.h>
#include <math.h>

#define Bb 16
#define Tt 12
#define Nn 300
#define Dd 64
#define T2 10
#define BT (Bb*Tt)        // 192
#define BW (Bb*T2)        // 160
#define QPAD 68           // padded row stride (multiple of 4 for float4 LDS)

// Scratch (static device allocations; no cudaMalloc allowed)
__device__ float g_S5[BT*5*Dd*Dd];     // partial S = sum_n sc_n f f^T per (bt,chunk)
__device__ float g_ss5[BT*5*Dd];       // partial ss = sum_n sc_n f[n,:]
__device__ float g_G[BW*Dd*Dd];        // per-window diag(sw^2) S_win w1
__device__ float g_v[BW*Dd];           // per-window sw^2 * ss_win

// ---- packed f32x2 helpers (sm_103a) ---------------------------------------
__device__ __forceinline__ unsigned long long pk2(float lo, float hi) {
    unsigned long long r;
    asm("mov.b64 %0, {%1, %2};" : "=l"(r) : "f"(lo), "f"(hi));
    return r;
}
__device__ __forceinline__ void unpk2(unsigned long long v, float& lo, float& hi) {
    asm("mov.b64 {%0, %1}, %2;" : "=f"(lo), "=f"(hi) : "l"(v));
}
__device__ __forceinline__ unsigned long long mul2(unsigned long long a,
                                                   unsigned long long b) {
    unsigned long long r;
    asm("mul.rn.f32x2 %0, %1, %2;" : "=l"(r) : "l"(a), "l"(b));
    return r;
}
__device__ __forceinline__ void fma2(unsigned long long& d,
                                     unsigned long long a,
                                     unsigned long long b) {
    asm("fma.rn.f32x2 %0, %1, %2, %0;" : "+l"(d) : "l"(a), "l"(b));
}

// ---------------------------------------------------------------------------
// Kernel A: per (bt, chunk of <=64 rows): sc_n = 1/max(||f_n .* sw||,eps),
//   partial S[j,d] = sum_n sc_n f[n,j] f[n,d]  (symmetric: upper-tri 4x4
//   thread-tiles, mirror written), partial ss[j].
// Norm fused into staging (width-16 shfl reduction) -> single barrier.
// ---------------------------------------------------------------------------
__global__ __launch_bounds__(256) void kA(const float* __restrict__ feat,
                                          const float* __restrict__ weights) {
    __shared__ float fs[64][Dd];
    __shared__ float scs[64];
    const int blk = blockIdx.x;
    const int bt  = blk / 5;
    const int c   = blk % 5;
    const int r0  = c * 64;
    const int nr  = min(64, Nn - r0);     // 64 or 44
    const int tid = threadIdx.x;
    const int c4  = tid & 15;             // float4 slot within a row

    // per-thread sigmoid(weights) segment (4 values, registers)
    float4 swv;
    swv.x = 1.0f / (1.0f + expf(-weights[c4*4 + 0]));
    swv.y = 1.0f / (1.0f + expf(-weights[c4*4 + 1]));
    swv.z = 1.0f / (1.0f + expf(-weights[c4*4 + 2]));
    swv.w = 1.0f / (1.0f + expf(-weights[c4*4 + 3]));

    const float* fbase = feat + ((size_t)bt * Nn + r0) * Dd;
    const int nv   = nr * 16;                 // float4 count
    const int trip = ((nv + 255) & ~255);     // uniform trip count for shfl

    // stage + fused weighted-L2 reduction (lanes 0..15 of each half-warp
    // cover one row; width-16 shfl reduces the sum of squares)
    for (int i = tid; i < trip; i += 256) {
        float4 v = make_float4(0.f, 0.f, 0.f, 0.f);
        const bool ok = i < nv;
        if (ok) v = ((const float4*)fbase)[i];
        const float px = v.x*swv.x, py = v.y*swv.y;
        const float pz = v.z*swv.z, pw = v.w*swv.w;
        float ps = px*px + py*py + pz*pz + pw*pw;
        ps += __shfl_xor_sync(0xffffffffu, ps, 1, 16);
        ps += __shfl_xor_sync(0xffffffffu, ps, 2, 16);
        ps += __shfl_xor_sync(0xffffffffu, ps, 4, 16);
        ps += __shfl_xor_sync(0xffffffffu, ps, 8, 16);
        if (ok) {
            ((float4*)fs)[i] = v;
            if (c4 == 0)
                scs[i >> 4] = 1.0f / fmaxf(sqrtf(ps), 1e-12f);
        }
    }
    __syncthreads();

    if (tid < 136) {
        // decode upper-triangular tile (rr <= cc) from linear index
        int t = tid, rr = 0;
        while (t >= 16 - rr) { t -= 16 - rr; ++rr; }
        const int cc = rr + t;

        // acc2[p][dd] packs rows (2p, 2p+1) of the 4x4 tile, column dd
        unsigned long long acc2[2][4];
        #pragma unroll
        for (int p = 0; p < 2; ++p)
            #pragma unroll
            for (int d = 0; d < 4; ++d) acc2[p][d] = 0ull;

        #pragma unroll 8
        for (int n = 0; n < nr; ++n) {
            const float  sc = scs[n];
            const float4 w4 = *(const float4*)&fs[n][rr*4];
            const float4 f4 = *(const float4*)&fs[n][cc*4];
            const unsigned long long scp = pk2(sc, sc);
            const unsigned long long sv01 = mul2(scp, pk2(w4.x, w4.y));
            const unsigned long long sv23 = mul2(scp, pk2(w4.z, w4.w));
            const float fv[4] = {f4.x, f4.y, f4.z, f4.w};
            #pragma unroll
            for (int d = 0; d < 4; ++d) {
                const unsigned long long fdd = pk2(fv[d], fv[d]);
                fma2(acc2[0][d], sv01, fdd);
                fma2(acc2[1][d], sv23, fdd);
            }
        }

        float acc[4][4];
        #pragma unroll
        for (int d = 0; d < 4; ++d) {
            unpk2(acc2[0][d], acc[0][d], acc[1][d]);
            unpk2(acc2[1][d], acc[2][d], acc[3][d]);
        }

        float* Sb = g_S5 + (size_t)blk * Dd * Dd;
        #pragma unroll
        for (int jj = 0; jj < 4; ++jj)
            *(float4*)&Sb[(rr*4 + jj)*Dd + cc*4] =
                make_float4(acc[jj][0], acc[jj][1], acc[jj][2], acc[jj][3]);
        if (rr != cc) {
            #pragma unroll
            for (int dd = 0; dd < 4; ++dd)
                *(float4*)&Sb[(cc*4 + dd)*Dd + rr*4] =
                    make_float4(acc[0][dd], acc[1][dd], acc[2][dd], acc[3][dd]);
        }
    } else if (tid >= 224 && tid < 240) {
        // warp 7 lanes 0..15: column sums ss[j] = sum_n sc_n f[n,j]
        const int jg = tid - 224;
        float ksa[4] = {0.f, 0.f, 0.f, 0.f};
        #pragma unroll 4
        for (int n = 0; n < nr; ++n) {
            const float  sc = scs[n];
            const float4 w4 = *(const float4*)&fs[n][jg*4];
            ksa[0] += sc*w4.x; ksa[1] += sc*w4.y;
            ksa[2] += sc*w4.z; ksa[3] += sc*w4.w;
        }
        *(float4*)&g_ss5[blk*Dd + jg*4] =
            make_float4(ksa[0], ksa[1], ksa[2], ksa[3]);
    }
}

// ---------------------------------------------------------------------------
// Kernel B: per window: Ms[j,:] = sw2[j] * sum of 15 partial S slices;
//   G = Ms @ w1;  v[j] = sw2[j] * sum of 15 partial ss. grid=160, 256 thr.
// ---------------------------------------------------------------------------
__global__ __launch_bounds__(256) void kB(const float* __restrict__ w1,
                                          const float* __restrict__ weights) {
    __shared__ float Ms[Dd*Dd];
    __shared__ float w1s[Dd*Dd];
    __shared__ float sw2[Dd];
    const int bw  = blockIdx.x;
    const int b   = bw / T2;
    const int t2  = bw % T2;
    const int bt0 = b * Tt + t2;
    const int tid = threadIdx.x;

    if (tid < Dd) {
        float s = 1.0f / (1.0f + expf(-weights[tid]));
        sw2[tid] = s * s;
    }
    __syncthreads();

    for (int i = tid; i < 1024; i += 256) {
        float4 m = make_float4(0.f, 0.f, 0.f, 0.f);
        #pragma unroll
        for (int s = 0; s < 3; ++s)
            #pragma unroll
            for (int cc = 0; cc < 5; ++cc) {
                const float4 v = ((const float4*)(g_S5 +
                    (size_t)((bt0 + s)*5 + cc) * Dd * Dd))[i];
                m.x += v.x; m.y += v.y; m.z += v.z; m.w += v.w;
            }
        const float s2 = sw2[i >> 4];
        m.x *= s2; m.y *= s2; m.z *= s2; m.w *= s2;
        ((float4*)Ms)[i]  = m;
        ((float4*)w1s)[i] = ((const float4*)w1)[i];
    }
    if (tid < Dd) {
        float s = 0.0f;
        #pragma unroll
        for (int sl = 0; sl < 15; ++sl)
            s += g_ss5[((bt0 + sl/5)*5 + sl%5)*Dd + tid];
        g_v[bw*Dd + tid] = sw2[tid] * s;
    }
    __syncthreads();

    const int d  = tid & 63;
    const int jg = tid >> 6;
    float* Gb = g_G + (size_t)bw * Dd * Dd;
    for (int j = jg*16; j < jg*16 + 16; ++j) {
        float s = 0.0f;
        #pragma unroll 16
        for (int k = 0; k < 64; ++k)
            s += Ms[j*64 + k] * w1s[k*64 + d];
        Gb[j*64 + d] = s;
    }
}

// ---------------------------------------------------------------------------
// Kernel C: per (window, 64-row tile): u = F@G; deg = F@v (fused into GEMM1);
//   r = relu(u/deg + b1); h = r@w2 + b2; s = F + h; LayerNorm -> out.
// 256 threads, 4x4 tile. Column-packed f32x2; vectorized R^T store;
// w2 + epilogue-feat register prefetch. grid = 800.
// ---------------------------------------------------------------------------
__global__ __launch_bounds__(256) void kC(const float* __restrict__ feat,
                                          const float* __restrict__ b1,
                                          const float* __restrict__ w2,
                                          const float* __restrict__ b2,
                                          const float* __restrict__ gamma,
                                          const float* __restrict__ beta,
                                          float* __restrict__ out) {
    __shared__ float Gs[Dd*Dd];      // G, later reused for w2
    __shared__ float QR[Dd*QPAD];    // F^T, later reused for R^T
    __shared__ float kss[Dd], b1s[Dd], b2s[Dd], gms[Dd], bts[Dd];

    const int blk  = blockIdx.x;
    const int bw   = blk / 5;
    const int tile = blk % 5;
    const int r0   = tile * 64;
    const int nr   = min(64, Nn - r0);
    const int b    = bw / T2;
    const int t2   = bw % T2;
    const int tid  = threadIdx.x;
    const int ty   = tid >> 4;       // row group 0..15
    const int tx   = tid & 15;       // col group 0..15

    const float* fb = feat + ((size_t)((b*Tt + t2 + 2)*Nn) + r0) * Dd;

    // stage F^T (zero-fill invalid rows), G, small vectors
    {
        const float4* qb = (const float4*)fb;
        for (int idx = tid; idx < 1024; idx += 256) {
            const int row = idx >> 4, c4 = idx & 15;
            float4 v = make_float4(0.f, 0.f, 0.f, 0.f);
            if (row < nr) v = qb[row*16 + c4];
            QR[(c4*4 + 0)*QPAD + row] = v.x;
            QR[(c4*4 + 1)*QPAD + row] = v.y;
            QR[(c4*4 + 2)*QPAD + row] = v.z;
            QR[(c4*4 + 3)*QPAD + row] = v.w;
        }
        const float4* Gb = (const float4*)(g_G + (size_t)bw * Dd * Dd);
        for (int i = tid; i < 1024; i += 256)
            ((float4*)Gs)[i] = Gb[i];
        if (tid < Dd) {
            kss[tid] = g_v[bw*Dd + tid];
            b1s[tid] = b1[tid]; b2s[tid] = b2[tid];
            gms[tid] = gamma[tid]; bts[tid] = beta[tid];
        }
    }

    // w2 register prefetch (LDG issued early; consumed after next barrier)
    float4 w2r[4];
    #pragma unroll
    for (int i = 0; i < 4; ++i)
        w2r[i] = ((const float4*)w2)[tid + i*256];

    __syncthreads();

    // GEMM1: u = F @ G, column-packed (acc2[i][p] = row i, cols 2p,2p+1);
    // deg = F @ v fused as 4 scalar FFMA chains.
    unsigned long long acc2[4][2];
    #pragma unroll
    for (int i = 0; i < 4; ++i) { acc2[i][0] = 0ull; acc2[i][1] = 0ull; }
    float dg[4] = {0.f, 0.f, 0.f, 0.f};

    #pragma unroll 8
    for (int k = 0; k < 64; ++k) {
        const float4 a4 = *(const float4*)&QR[k*QPAD + ty*4];
        const float4 b4 = *(const float4*)&Gs[k*Dd + tx*4];
        const float  vk = kss[k];
        const unsigned long long b01 = pk2(b4.x, b4.y);   // register pair
        const unsigned long long b23 = pk2(b4.z, b4.w);   // register pair
        const float av[4] = {a4.x, a4.y, a4.z, a4.w};
        #pragma unroll
        for (int i = 0; i < 4; ++i) {
            const unsigned long long ad = pk2(av[i], av[i]);
            fma2(acc2[i][0], ad, b01);
            fma2(acc2[i][1], ad, b23);
            dg[i] += av[i] * vk;
        }
    }

    float acc[4][4];
    #pragma unroll
    for (int i = 0; i < 4; ++i) {
        unpk2(acc2[i][0], acc[i][0], acc[i][1]);
        unpk2(acc2[i][1], acc[i][2], acc[i][3]);
    }

    // relu(u/deg + b1) -> registers
    float r[4][4];
    #pragma unroll
    for (int i = 0; i < 4; ++i) {
        const float dinv = (dg[i] == 0.0f) ? 0.0f : 1.0f / dg[i];
        #pragma unroll
        for (int j = 0; j < 4; ++j)
            r[i][j] = fmaxf(acc[i][j] * dinv + b1s[tx*4 + j], 0.0f);
    }
    __syncthreads();   // everyone done reading QR/Gs

    // store R^T as float4 columns (thread owns full R^T row segments),
    // store prefetched w2 into Gs
    #pragma unroll
    for (int j = 0; j < 4; ++j)
        *(float4*)&QR[(tx*4 + j)*QPAD + ty*4] =
            make_float4(r[0][j], r[1][j], r[2][j], r[3][j]);
    #pragma unroll
    for (int i = 0; i < 4; ++i)
        ((float4*)Gs)[tid + i*256] = w2r[i];
    __syncthreads();

    // prefetch epilogue residual reads (hidden under GEMM2)
    float4 fpre[4];
    #pragma unroll
    for (int i = 0; i < 4; ++i) {
        const int row = ty*4 + i;
        fpre[i] = make_float4(0.f, 0.f, 0.f, 0.f);
        if (row < nr) fpre[i] = ((const float4*)fb)[row*16 + tx];
    }

    // GEMM2: h = R @ w2 (column-packed)
    #pragma unroll
    for (int i = 0; i < 4; ++i) { acc2[i][0] = 0ull; acc2[i][1] = 0ull; }

    #pragma unroll 8
    for (int k = 0; k < 64; ++k) {
        const float4 a4 = *(const float4*)&QR[k*QPAD + ty*4];
        const float4 b4 = *(const float4*)&Gs[k*Dd + tx*4];
        const unsigned long long b01 = pk2(b4.x, b4.y);
        const unsigned long long b23 = pk2(b4.z, b4.w);
        const float av[4] = {a4.x, a4.y, a4.z, a4.w};
        #pragma unroll
        for (int i = 0; i < 4; ++i) {
            const unsigned long long ad = pk2(av[i], av[i]);
            fma2(acc2[i][0], ad, b01);
            fma2(acc2[i][1], ad, b23);
        }
    }
    #pragma unroll
    for (int i = 0; i < 4; ++i) {
        unpk2(acc2[i][0], acc[i][0], acc[i][1]);
        unpk2(acc2[i][1], acc[i][2], acc[i][3]);
    }

    // epilogue: residual + bias, LayerNorm per row (16 threads/row, width-16 shfl)
    float* ob = out + ((size_t)bw * Nn + r0) * Dd;
    #pragma unroll
    for (int i = 0; i < 4; ++i) {
        const int row = ty*4 + i;
        const bool valid = row < nr;
        const float4 f4 = fpre[i];
        float h0 = acc[i][0] + f4.x + b2s[tx*4 + 0];
        float h1 = acc[i][1] + f4.y + b2s[tx*4 + 1];
        float h2 = acc[i][2] + f4.z + b2s[tx*4 + 2];
        float h3 = acc[i][3] + f4.w + b2s[tx*4 + 3];

        float s = h0 + h1 + h2 + h3;
        #pragma unroll
        for (int m = 1; m < 16; m <<= 1)
            s += __shfl_xor_sync(0xffffffffu, s, m, 16);
        const float mu = s * (1.0f / 64.0f);

        float a0 = h0 - mu, a1 = h1 - mu, a2 = h2 - mu, a3 = h3 - mu;
        float vs = a0*a0 + a1*a1 + a2*a2 + a3*a3;
        #pragma unroll
        for (int m = 1; m < 16; m <<= 1)
            vs += __shfl_xor_sync(0xffffffffu, vs, m, 16);
        const float rstd = rsqrtf(vs * (1.0f / 64.0f) + 1e-5f);

        if (valid) {
            float4 o;
            o.x = a0 * rstd * gms[tx*4 + 0] + bts[tx*4 + 0];
            o.y = a1 * rstd * gms[tx*4 + 1] + bts[tx*4 + 1];
            o.z = a2 * rstd * gms[tx*4 + 2] + bts[tx*4 + 2];
            o.w = a3 * rstd * gms[tx*4 + 3] + bts[tx*4 + 3];
            ((float4*)ob)[row*16 + tx] = o;
        }
    }
}

extern "C" void kernel_launch(void* const* d_in, const int* in_sizes, int n_in,
                              void* d_out, int out_size) {
    const float* feat    = (const float*)d_in[0];
    const float* weights = (const float*)d_in[1];
    const float* w1      = (const float*)d_in[2];
    const float* b1      = (const float*)d_in[3];
    const float* w2      = (const float*)d_in[4];
    const float* b2      = (const float*)d_in[5];
    const float* gamma   = (const float*)d_in[6];
    const float* beta    = (const float*)d_in[7];
    float* out = (float*)d_out;

    kA<<<BT*5, 256>>>(feat, weights);
    kB<<<BW, 256>>>(w1, weights);
    kC<<<BW*5, 256>>>(feat, b1, w2, b2, gamma, beta, out);
}

// round 12
// speedup vs baseline: 1.0195x; 1.0195x over previous
#include <cuda_runtime.h>
#include <math.h>

#define Bb 16
#define Tt 12
#define Nn 300
#define Dd 64
#define T2 10
#define BT (Bb*Tt)        // 192
#define BW (Bb*T2)        // 160
#define QPAD 68           // padded row stride (multiple of 4 for float4 LDS)

// Scratch (static device allocations; no cudaMalloc allowed)
__device__ float g_S5[BT*5*Dd*Dd];     // partial S = sum_n sc_n f f^T per (bt,chunk)
__device__ float g_ss5[BT*5*Dd];       // partial ss = sum_n sc_n f[n,:]
__device__ float g_G[BW*Dd*Dd];        // per-window diag(sw^2) S_win w1
__device__ float g_v[BW*Dd];           // per-window sw^2 * ss_win

// ---- packed f32x2 helpers (sm_103a) ---------------------------------------
__device__ __forceinline__ unsigned long long pk2(float lo, float hi) {
    unsigned long long r;
    asm("mov.b64 %0, {%1, %2};" : "=l"(r) : "f"(lo), "f"(hi));
    return r;
}
__device__ __forceinline__ void unpk2(unsigned long long v, float& lo, float& hi) {
    asm("mov.b64 {%0, %1}, %2;" : "=f"(lo), "=f"(hi) : "l"(v));
}
__device__ __forceinline__ unsigned long long mul2(unsigned long long a,
                                                   unsigned long long b) {
    unsigned long long r;
    asm("mul.rn.f32x2 %0, %1, %2;" : "=l"(r) : "l"(a), "l"(b));
    return r;
}
__device__ __forceinline__ void fma2(unsigned long long& d,
                                     unsigned long long a,
                                     unsigned long long b) {
    asm("fma.rn.f32x2 %0, %1, %2, %0;" : "+l"(d) : "l"(a), "l"(b));
}

// ---------------------------------------------------------------------------
// Kernel A: per (bt, chunk of <=64 rows): sc_n = 1/max(||f_n .* sw||,eps),
//   partial S[j,d] = sum_n sc_n f[n,j] f[n,d]  (symmetric: upper-tri 4x4
//   thread-tiles, mirror written), partial ss[j].
// 192 threads: warps 0-4 = 136 triangle tiles, warp 5 lanes 0-15 = ss.
// Norm fused into staging (width-16 shfl reduction) -> single barrier.
// ---------------------------------------------------------------------------
__global__ __launch_bounds__(192) void kA(const float* __restrict__ feat,
                                          const float* __restrict__ weights) {
    __shared__ float fs[64][Dd];
    __shared__ float scs[64];
    const int blk = blockIdx.x;
    const int bt  = blk / 5;
    const int c   = blk % 5;
    const int r0  = c * 64;
    const int nr  = min(64, Nn - r0);     // 64 or 44
    const int tid = threadIdx.x;
    const int c4  = tid & 15;             // float4 slot within a row

    // per-thread sigmoid(weights) segment (4 values, registers)
    float4 swv;
    swv.x = 1.0f / (1.0f + expf(-weights[c4*4 + 0]));
    swv.y = 1.0f / (1.0f + expf(-weights[c4*4 + 1]));
    swv.z = 1.0f / (1.0f + expf(-weights[c4*4 + 2]));
    swv.w = 1.0f / (1.0f + expf(-weights[c4*4 + 3]));

    const float* fbase = feat + ((size_t)bt * Nn + r0) * Dd;
    const int nv   = nr * 16;                       // float4 count
    const int trip = ((nv + 191) / 192) * 192;      // uniform trip for shfl

    // stage + fused weighted-L2 reduction (lanes 0..15 of each half-warp
    // cover one row; width-16 shfl reduces the sum of squares)
    for (int i = tid; i < trip; i += 192) {
        float4 v = make_float4(0.f, 0.f, 0.f, 0.f);
        const bool ok = i < nv;
        if (ok) v = ((const float4*)fbase)[i];
        const float px = v.x*swv.x, py = v.y*swv.y;
        const float pz = v.z*swv.z, pw = v.w*swv.w;
        float ps = px*px + py*py + pz*pz + pw*pw;
        ps += __shfl_xor_sync(0xffffffffu, ps, 1, 16);
        ps += __shfl_xor_sync(0xffffffffu, ps, 2, 16);
        ps += __shfl_xor_sync(0xffffffffu, ps, 4, 16);
        ps += __shfl_xor_sync(0xffffffffu, ps, 8, 16);
        if (ok) {
            ((float4*)fs)[i] = v;
            if (c4 == 0)
                scs[i >> 4] = 1.0f / fmaxf(sqrtf(ps), 1e-12f);
        }
    }
    __syncthreads();

    if (tid < 136) {
        // decode upper-triangular tile (rr <= cc) from linear index
        int t = tid, rr = 0;
        while (t >= 16 - rr) { t -= 16 - rr; ++rr; }
        const int cc = rr + t;

        // acc2[p][dd] packs rows (2p, 2p+1) of the 4x4 tile, column dd
        unsigned long long acc2[2][4];
        #pragma unroll
        for (int p = 0; p < 2; ++p)
            #pragma unroll
            for (int d = 0; d < 4; ++d) acc2[p][d] = 0ull;

        #pragma unroll 8
        for (int n = 0; n < nr; ++n) {
            const float  sc = scs[n];
            const float4 w4 = *(const float4*)&fs[n][rr*4];
            const float4 f4 = *(const float4*)&fs[n][cc*4];
            const unsigned long long scp = pk2(sc, sc);
            const unsigned long long sv01 = mul2(scp, pk2(w4.x, w4.y));
            const unsigned long long sv23 = mul2(scp, pk2(w4.z, w4.w));
            const float fv[4] = {f4.x, f4.y, f4.z, f4.w};
            #pragma unroll
            for (int d = 0; d < 4; ++d) {
                const unsigned long long fdd = pk2(fv[d], fv[d]);
                fma2(acc2[0][d], sv01, fdd);
                fma2(acc2[1][d], sv23, fdd);
            }
        }

        float acc[4][4];
        #pragma unroll
        for (int d = 0; d < 4; ++d) {
            unpk2(acc2[0][d], acc[0][d], acc[1][d]);
            unpk2(acc2[1][d], acc[2][d], acc[3][d]);
        }

        float* Sb = g_S5 + (size_t)blk * Dd * Dd;
        #pragma unroll
        for (int jj = 0; jj < 4; ++jj)
            *(float4*)&Sb[(rr*4 + jj)*Dd + cc*4] =
                make_float4(acc[jj][0], acc[jj][1], acc[jj][2], acc[jj][3]);
        if (rr != cc) {
            #pragma unroll
            for (int dd = 0; dd < 4; ++dd)
                *(float4*)&Sb[(cc*4 + dd)*Dd + rr*4] =
                    make_float4(acc[0][dd], acc[1][dd], acc[2][dd], acc[3][dd]);
        }
    } else if (tid >= 160 && tid < 176) {
        // warp 5 lanes 0..15: column sums ss[j] = sum_n sc_n f[n,j]
        const int jg = tid - 160;
        float ksa[4] = {0.f, 0.f, 0.f, 0.f};
        #pragma unroll 4
        for (int n = 0; n < nr; ++n) {
            const float  sc = scs[n];
            const float4 w4 = *(const float4*)&fs[n][jg*4];
            ksa[0] += sc*w4.x; ksa[1] += sc*w4.y;
            ksa[2] += sc*w4.z; ksa[3] += sc*w4.w;
        }
        *(float4*)&g_ss5[blk*Dd + jg*4] =
            make_float4(ksa[0], ksa[1], ksa[2], ksa[3]);
    }
}

// ---------------------------------------------------------------------------
// Kernel B: per window: Ms[j,:] = sw2[j] * sum of 15 partial S slices;
//   G = Ms @ w1;  v[j] = sw2[j] * sum of 15 partial ss. grid=160, 256 thr.
// ---------------------------------------------------------------------------
__global__ __launch_bounds__(256) void kB(const float* __restrict__ w1,
                                          const float* __restrict__ weights) {
    __shared__ float Ms[Dd*Dd];
    __shared__ float w1s[Dd*Dd];
    __shared__ float sw2[Dd];
    const int bw  = blockIdx.x;
    const int b   = bw / T2;
    const int t2  = bw % T2;
    const int bt0 = b * Tt + t2;
    const int tid = threadIdx.x;

    if (tid < Dd) {
        float s = 1.0f / (1.0f + expf(-weights[tid]));
        sw2[tid] = s * s;
    }
    __syncthreads();

    for (int i = tid; i < 1024; i += 256) {
        float4 m = make_float4(0.f, 0.f, 0.f, 0.f);
        #pragma unroll
        for (int s = 0; s < 3; ++s)
            #pragma unroll
            for (int cc = 0; cc < 5; ++cc) {
                const float4 v = ((const float4*)(g_S5 +
                    (size_t)((bt0 + s)*5 + cc) * Dd * Dd))[i];
                m.x += v.x; m.y += v.y; m.z += v.z; m.w += v.w;
            }
        const float s2 = sw2[i >> 4];
        m.x *= s2; m.y *= s2; m.z *= s2; m.w *= s2;
        ((float4*)Ms)[i]  = m;
        ((float4*)w1s)[i] = ((const float4*)w1)[i];
    }
    if (tid < Dd) {
        float s = 0.0f;
        #pragma unroll
        for (int sl = 0; sl < 15; ++sl)
            s += g_ss5[((bt0 + sl/5)*5 + sl%5)*Dd + tid];
        g_v[bw*Dd + tid] = sw2[tid] * s;
    }
    __syncthreads();

    const int d  = tid & 63;
    const int jg = tid >> 6;
    float* Gb = g_G + (size_t)bw * Dd * Dd;
    for (int j = jg*16; j < jg*16 + 16; ++j) {
        float s = 0.0f;
        #pragma unroll 16
        for (int k = 0; k < 64; ++k)
            s += Ms[j*64 + k] * w1s[k*64 + d];
        Gb[j*64 + d] = s;
    }
}

// ---------------------------------------------------------------------------
// Kernel C: per (window, 64-row tile): u = F@G; deg = F@v (fused into GEMM1);
//   r = relu(u/deg + b1); h = r@w2 + b2; s = F + h; LayerNorm -> out.
// 256 threads, 4x4 tile. Column-packed f32x2; vectorized R^T store;
// w2 register prefetch (no epilogue prefetch: register pressure). grid=800.
// ---------------------------------------------------------------------------
__global__ __launch_bounds__(256) void kC(const float* __restrict__ feat,
                                          const float* __restrict__ b1,
                                          const float* __restrict__ w2,
                                          const float* __restrict__ b2,
                                          const float* __restrict__ gamma,
                                          const float* __restrict__ beta,
                                          float* __restrict__ out) {
    __shared__ float Gs[Dd*Dd];      // G, later reused for w2
    __shared__ float QR[Dd*QPAD];    // F^T, later reused for R^T
    __shared__ float kss[Dd], b1s[Dd], b2s[Dd], gms[Dd], bts[Dd];

    const int blk  = blockIdx.x;
    const int bw   = blk / 5;
    const int tile = blk % 5;
    const int r0   = tile * 64;
    const int nr   = min(64, Nn - r0);
    const int b    = bw / T2;
    const int t2   = bw % T2;
    const int tid  = threadIdx.x;
    const int ty   = tid >> 4;       // row group 0..15
    const int tx   = tid & 15;       // col group 0..15

    const float* fb = feat + ((size_t)((b*Tt + t2 + 2)*Nn) + r0) * Dd;

    // stage F^T (zero-fill invalid rows), G, small vectors
    {
        const float4* qb = (const float4*)fb;
        for (int idx = tid; idx < 1024; idx += 256) {
            const int row = idx >> 4, c4 = idx & 15;
            float4 v = make_float4(0.f, 0.f, 0.f, 0.f);
            if (row < nr) v = qb[row*16 + c4];
            QR[(c4*4 + 0)*QPAD + row] = v.x;
            QR[(c4*4 + 1)*QPAD + row] = v.y;
            QR[(c4*4 + 2)*QPAD + row] = v.z;
            QR[(c4*4 + 3)*QPAD + row] = v.w;
        }
        const float4* Gb = (const float4*)(g_G + (size_t)bw * Dd * Dd);
        for (int i = tid; i < 1024; i += 256)
            ((float4*)Gs)[i] = Gb[i];
        if (tid < Dd) {
            kss[tid] = g_v[bw*Dd + tid];
            b1s[tid] = b1[tid]; b2s[tid] = b2[tid];
            gms[tid] = gamma[tid]; bts[tid] = beta[tid];
        }
    }

    // w2 register prefetch (LDG issued early; consumed after next barrier)
    float4 w2r[4];
    #pragma unroll
    for (int i = 0; i < 4; ++i)
        w2r[i] = ((const float4*)w2)[tid + i*256];

    __syncthreads();

    // GEMM1: u = F @ G, column-packed (acc2[i][p] = row i, cols 2p,2p+1);
    // deg = F @ v fused as 4 scalar FFMA chains.
    unsigned long long acc2[4][2];
    #pragma unroll
    for (int i = 0; i < 4; ++i) { acc2[i][0] = 0ull; acc2[i][1] = 0ull; }
    float dg[4] = {0.f, 0.f, 0.f, 0.f};

    #pragma unroll 8
    for (int k = 0; k < 64; ++k) {
        const float4 a4 = *(const float4*)&QR[k*QPAD + ty*4];
        const float4 b4 = *(const float4*)&Gs[k*Dd + tx*4];
        const float  vk = kss[k];
        const unsigned long long b01 = pk2(b4.x, b4.y);   // register pair
        const unsigned long long b23 = pk2(b4.z, b4.w);   // register pair
        const float av[4] = {a4.x, a4.y, a4.z, a4.w};
        #pragma unroll
        for (int i = 0; i < 4; ++i) {
            const unsigned long long ad = pk2(av[i], av[i]);
            fma2(acc2[i][0], ad, b01);
            fma2(acc2[i][1], ad, b23);
            dg[i] += av[i] * vk;
        }
    }

    float acc[4][4];
    #pragma unroll
    for (int i = 0; i < 4; ++i) {
        unpk2(acc2[i][0], acc[i][0], acc[i][1]);
        unpk2(acc2[i][1], acc[i][2], acc[i][3]);
    }

    // relu(u/deg + b1) -> registers
    float r[4][4];
    #pragma unroll
    for (int i = 0; i < 4; ++i) {
        const float dinv = (dg[i] == 0.0f) ? 0.0f : 1.0f / dg[i];
        #pragma unroll
        for (int j = 0; j < 4; ++j)
            r[i][j] = fmaxf(acc[i][j] * dinv + b1s[tx*4 + j], 0.0f);
    }
    __syncthreads();   // everyone done reading QR/Gs

    // store R^T as float4 columns (thread owns full R^T row segments),
    // store prefetched w2 into Gs
    #pragma unroll
    for (int j = 0; j < 4; ++j)
        *(float4*)&QR[(tx*4 + j)*QPAD + ty*4] =
            make_float4(r[0][j], r[1][j], r[2][j], r[3][j]);
    #pragma unroll
    for (int i = 0; i < 4; ++i)
        ((float4*)Gs)[tid + i*256] = w2r[i];
    __syncthreads();

    // GEMM2: h = R @ w2 (column-packed)
    #pragma unroll
    for (int i = 0; i < 4; ++i) { acc2[i][0] = 0ull; acc2[i][1] = 0ull; }

    #pragma unroll 8
    for (int k = 0; k < 64; ++k) {
        const float4 a4 = *(const float4*)&QR[k*QPAD + ty*4];
        const float4 b4 = *(const float4*)&Gs[k*Dd + tx*4];
        const unsigned long long b01 = pk2(b4.x, b4.y);
        const unsigned long long b23 = pk2(b4.z, b4.w);
        const float av[4] = {a4.x, a4.y, a4.z, a4.w};
        #pragma unroll
        for (int i = 0; i < 4; ++i) {
            const unsigned long long ad = pk2(av[i], av[i]);
            fma2(acc2[i][0], ad, b01);
            fma2(acc2[i][1], ad, b23);
        }
    }
    #pragma unroll
    for (int i = 0; i < 4; ++i) {
        unpk2(acc2[i][0], acc[i][0], acc[i][1]);
        unpk2(acc2[i][1], acc[i][2], acc[i][3]);
    }

    // epilogue: residual + bias, LayerNorm per row (16 threads/row, width-16 shfl)
    float* ob = out + ((size_t)bw * Nn + r0) * Dd;
    #pragma unroll
    for (int i = 0; i < 4; ++i) {
        const int row = ty*4 + i;
        const bool valid = row < nr;
        float4 f4 = make_float4(0.f, 0.f, 0.f, 0.f);
        if (valid) f4 = ((const float4*)fb)[row*16 + tx];
        float h0 = acc[i][0] + f4.x + b2s[tx*4 + 0];
        float h1 = acc[i][1] + f4.y + b2s[tx*4 + 1];
        float h2 = acc[i][2] + f4.z + b2s[tx*4 + 2];
        float h3 = acc[i][3] + f4.w + b2s[tx*4 + 3];

        float s = h0 + h1 + h2 + h3;
        #pragma unroll
        for (int m = 1; m < 16; m <<= 1)
            s += __shfl_xor_sync(0xffffffffu, s, m, 16);
        const float mu = s * (1.0f / 64.0f);

        float a0 = h0 - mu, a1 = h1 - mu, a2 = h2 - mu, a3 = h3 - mu;
        float vs = a0*a0 + a1*a1 + a2*a2 + a3*a3;
        #pragma unroll
        for (int m = 1; m < 16; m <<= 1)
            vs += __shfl_xor_sync(0xffffffffu, vs, m, 16);
        const float rstd = rsqrtf(vs * (1.0f / 64.0f) + 1e-5f);

        if (valid) {
            float4 o;
            o.x = a0 * rstd * gms[tx*4 + 0] + bts[tx*4 + 0];
            o.y = a1 * rstd * gms[tx*4 + 1] + bts[tx*4 + 1];
            o.z = a2 * rstd * gms[tx*4 + 2] + bts[tx*4 + 2];
            o.w = a3 * rstd * gms[tx*4 + 3] + bts[tx*4 + 3];
            ((float4*)ob)[row*16 + tx] = o;
        }
    }
}

extern "C" void kernel_launch(void* const* d_in, const int* in_sizes, int n_in,
                              void* d_out, int out_size) {
    const float* feat    = (const float*)d_in[0];
    const float* weights = (const float*)d_in[1];
    const float* w1      = (const float*)d_in[2];
    const float* b1      = (const float*)d_in[3];
    const float* w2      = (const float*)d_in[4];
    const float* b2      = (const float*)d_in[5];
    const float* gamma   = (const float*)d_in[6];
    const float* beta    = (const float*)d_in[7];
    float* out = (float*)d_out;

    kA<<<BT*5, 192>>>(feat, weights);
    kB<<<BW, 256>>>(w1, weights);
    kC<<<BW*5, 256>>>(feat, b1, w2, b2, gamma, beta, out);
}

// round 14
// speedup vs baseline: 1.0239x; 1.0043x over previous
#include <cuda_runtime.h>
#include <math.h>

#define Bb 16
#define Tt 12
#define Nn 300
#define Dd 64
#define T2 10
#define BT (Bb*Tt)        // 192
#define BW (Bb*T2)        // 160
#define QPAD 68           // padded row stride (multiple of 4 for float4 LDS)

// Scratch (static device allocations; no cudaMalloc allowed)
__device__ float g_S5[BT*5*Dd*Dd];     // partial S = sum_n sc_n f f^T per (bt,chunk)
__device__ float g_ss5[BT*5*Dd];       // partial ss = sum_n sc_n f[n,:]
__device__ float g_G[BW*Dd*Dd];        // per-window diag(sw^2) S_win w1
__device__ float g_v[BW*Dd];           // per-window sw^2 * ss_win

// ---- packed f32x2 helpers (sm_103a) ---------------------------------------
__device__ __forceinline__ unsigned long long pk2(float lo, float hi) {
    unsigned long long r;
    asm("mov.b64 %0, {%1, %2};" : "=l"(r) : "f"(lo), "f"(hi));
    return r;
}
__device__ __forceinline__ void unpk2(unsigned long long v, float& lo, float& hi) {
    asm("mov.b64 {%0, %1}, %2;" : "=f"(lo), "=f"(hi) : "l"(v));
}
__device__ __forceinline__ unsigned long long mul2(unsigned long long a,
                                                   unsigned long long b) {
    unsigned long long r;
    asm("mul.rn.f32x2 %0, %1, %2;" : "=l"(r) : "l"(a), "l"(b));
    return r;
}
__device__ __forceinline__ void fma2(unsigned long long& d,
                                     unsigned long long a,
                                     unsigned long long b) {
    asm("fma.rn.f32x2 %0, %1, %2, %0;" : "+l"(d) : "l"(a), "l"(b));
}

// ---------------------------------------------------------------------------
// Kernel A (R10-proven): per (bt, chunk of <=64 rows):
//   sc_n = 1/max(||f_n .* sw||,eps); partial S (symmetric, upper-tri 4x4
//   tiles mirrored); partial ss. 256 threads, norm fused into staging.
// ---------------------------------------------------------------------------
__global__ __launch_bounds__(256) void kA(const float* __restrict__ feat,
                                          const float* __restrict__ weights) {
    __shared__ float fs[64][Dd];
    __shared__ float scs[64];
    const int blk = blockIdx.x;
    const int bt  = blk / 5;
    const int c   = blk % 5;
    const int r0  = c * 64;
    const int nr  = min(64, Nn - r0);     // 64 or 44
    const int tid = threadIdx.x;
    const int c4  = tid & 15;             // float4 slot within a row

    float4 swv;
    swv.x = 1.0f / (1.0f + expf(-weights[c4*4 + 0]));
    swv.y = 1.0f / (1.0f + expf(-weights[c4*4 + 1]));
    swv.z = 1.0f / (1.0f + expf(-weights[c4*4 + 2]));
    swv.w = 1.0f / (1.0f + expf(-weights[c4*4 + 3]));

    const float* fbase = feat + ((size_t)bt * Nn + r0) * Dd;
    const int nv   = nr * 16;                 // float4 count
    const int trip = ((nv + 255) & ~255);     // uniform trip count for shfl

    for (int i = tid; i < trip; i += 256) {
        float4 v = make_float4(0.f, 0.f, 0.f, 0.f);
        const bool ok = i < nv;
        if (ok) v = ((const float4*)fbase)[i];
        const float px = v.x*swv.x, py = v.y*swv.y;
        const float pz = v.z*swv.z, pw = v.w*swv.w;
        float ps = px*px + py*py + pz*pz + pw*pw;
        ps += __shfl_xor_sync(0xffffffffu, ps, 1, 16);
        ps += __shfl_xor_sync(0xffffffffu, ps, 2, 16);
        ps += __shfl_xor_sync(0xffffffffu, ps, 4, 16);
        ps += __shfl_xor_sync(0xffffffffu, ps, 8, 16);
        if (ok) {
            ((float4*)fs)[i] = v;
            if (c4 == 0)
                scs[i >> 4] = 1.0f / fmaxf(sqrtf(ps), 1e-12f);
        }
    }
    __syncthreads();

    if (tid < 136) {
        int t = tid, rr = 0;
        while (t >= 16 - rr) { t -= 16 - rr; ++rr; }
        const int cc = rr + t;

        unsigned long long acc2[2][4];
        #pragma unroll
        for (int p = 0; p < 2; ++p)
            #pragma unroll
            for (int d = 0; d < 4; ++d) acc2[p][d] = 0ull;

        #pragma unroll 8
        for (int n = 0; n < nr; ++n) {
            const float  sc = scs[n];
            const float4 w4 = *(const float4*)&fs[n][rr*4];
            const float4 f4 = *(const float4*)&fs[n][cc*4];
            const unsigned long long scp = pk2(sc, sc);
            const unsigned long long sv01 = mul2(scp, pk2(w4.x, w4.y));
            const unsigned long long sv23 = mul2(scp, pk2(w4.z, w4.w));
            const float fv[4] = {f4.x, f4.y, f4.z, f4.w};
            #pragma unroll
            for (int d = 0; d < 4; ++d) {
                const unsigned long long fdd = pk2(fv[d], fv[d]);
                fma2(acc2[0][d], sv01, fdd);
                fma2(acc2[1][d], sv23, fdd);
            }
        }

        float acc[4][4];
        #pragma unroll
        for (int d = 0; d < 4; ++d) {
            unpk2(acc2[0][d], acc[0][d], acc[1][d]);
            unpk2(acc2[1][d], acc[2][d], acc[3][d]);
        }

        float* Sb = g_S5 + (size_t)blk * Dd * Dd;
        #pragma unroll
        for (int jj = 0; jj < 4; ++jj)
            *(float4*)&Sb[(rr*4 + jj)*Dd + cc*4] =
                make_float4(acc[jj][0], acc[jj][1], acc[jj][2], acc[jj][3]);
        if (rr != cc) {
            #pragma unroll
            for (int dd = 0; dd < 4; ++dd)
                *(float4*)&Sb[(cc*4 + dd)*Dd + rr*4] =
                    make_float4(acc[0][dd], acc[1][dd], acc[2][dd], acc[3][dd]);
        }
    } else if (tid >= 224 && tid < 240) {
        const int jg = tid - 224;
        float ksa[4] = {0.f, 0.f, 0.f, 0.f};
        #pragma unroll 4
        for (int n = 0; n < nr; ++n) {
            const float  sc = scs[n];
            const float4 w4 = *(const float4*)&fs[n][jg*4];
            ksa[0] += sc*w4.x; ksa[1] += sc*w4.y;
            ksa[2] += sc*w4.z; ksa[3] += sc*w4.w;
        }
        *(float4*)&g_ss5[blk*Dd + jg*4] =
            make_float4(ksa[0], ksa[1], ksa[2], ksa[3]);
    }
}

// ---------------------------------------------------------------------------
// Kernel B: per window: Ms[j,:] = sw2[j] * sum of 15 partial S slices;
//   G = Ms @ w1;  v[j] = sw2[j] * sum of 15 partial ss. grid=160, 256 thr.
// ---------------------------------------------------------------------------
__global__ __launch_bounds__(256) void kB(const float* __restrict__ w1,
                                          const float* __restrict__ weights) {
    __shared__ float Ms[Dd*Dd];
    __shared__ float w1s[Dd*Dd];
    __shared__ float sw2[Dd];
    const int bw  = blockIdx.x;
    const int b   = bw / T2;
    const int t2  = bw % T2;
    const int bt0 = b * Tt + t2;
    const int tid = threadIdx.x;

    if (tid < Dd) {
        float s = 1.0f / (1.0f + expf(-weights[tid]));
        sw2[tid] = s * s;
    }
    __syncthreads();

    for (int i = tid; i < 1024; i += 256) {
        float4 m = make_float4(0.f, 0.f, 0.f, 0.f);
        #pragma unroll
        for (int s = 0; s < 3; ++s)
            #pragma unroll
            for (int cc = 0; cc < 5; ++cc) {
                const float4 v = ((const float4*)(g_S5 +
                    (size_t)((bt0 + s)*5 + cc) * Dd * Dd))[i];
                m.x += v.x; m.y += v.y; m.z += v.z; m.w += v.w;
            }
        const float s2 = sw2[i >> 4];
        m.x *= s2; m.y *= s2; m.z *= s2; m.w *= s2;
        ((float4*)Ms)[i]  = m;
        ((float4*)w1s)[i] = ((const float4*)w1)[i];
    }
    if (tid < Dd) {
        float s = 0.0f;
        #pragma unroll
        for (int sl = 0; sl < 15; ++sl)
            s += g_ss5[((bt0 + sl/5)*5 + sl%5)*Dd + tid];
        g_v[bw*Dd + tid] = sw2[tid] * s;
    }
    __syncthreads();

    const int d  = tid & 63;
    const int jg = tid >> 6;
    float* Gb = g_G + (size_t)bw * Dd * Dd;
    for (int j = jg*16; j < jg*16 + 16; ++j) {
        float s = 0.0f;
        #pragma unroll 16
        for (int k = 0; k < 64; ++k)
            s += Ms[j*64 + k] * w1s[k*64 + d];
        Gb[j*64 + d] = s;
    }
}

// ---------------------------------------------------------------------------
// Kernel C: per (window, 64-row tile): u = F@G; deg = F@v (fused into GEMM1);
//   r = relu(u/deg + b1); h = r@w2 + b2; s = F + h; LayerNorm -> out.
// 256 threads, 4x4 tile, column-packed f32x2, vectorized R^T store.
// min 3 blocks/SM forced (register cap) for occupancy. grid = 800.
// ---------------------------------------------------------------------------
__global__ __launch_bounds__(256, 3) void kC(const float* __restrict__ feat,
                                             const float* __restrict__ b1,
                                             const float* __restrict__ w2,
                                             const float* __restrict__ b2,
                                             const float* __restrict__ gamma,
                                             const float* __restrict__ beta,
                                             float* __restrict__ out) {
    __shared__ float Gs[Dd*Dd];      // G, later reused for w2
    __shared__ float QR[Dd*QPAD];    // F^T, later reused for R^T
    __shared__ float kss[Dd], b1s[Dd], b2s[Dd], gms[Dd], bts[Dd];

    const int blk  = blockIdx.x;
    const int bw   = blk / 5;
    const int tile = blk % 5;
    const int r0   = tile * 64;
    const int nr   = min(64, Nn - r0);
    const int b    = bw / T2;
    const int t2   = bw % T2;
    const int tid  = threadIdx.x;
    const int ty   = tid >> 4;       // row group 0..15
    const int tx   = tid & 15;       // col group 0..15

    const float* fb = feat + ((size_t)((b*Tt + t2 + 2)*Nn) + r0) * Dd;

    // stage F^T (zero-fill invalid rows), G, small vectors
    {
        const float4* qb = (const float4*)fb;
        for (int idx = tid; idx < 1024; idx += 256) {
            const int row = idx >> 4, c4 = idx & 15;
            float4 v = make_float4(0.f, 0.f, 0.f, 0.f);
            if (row < nr) v = qb[row*16 + c4];
            QR[(c4*4 + 0)*QPAD + row] = v.x;
            QR[(c4*4 + 1)*QPAD + row] = v.y;
            QR[(c4*4 + 2)*QPAD + row] = v.z;
            QR[(c4*4 + 3)*QPAD + row] = v.w;
        }
        const float4* Gb = (const float4*)(g_G + (size_t)bw * Dd * Dd);
        for (int i = tid; i < 1024; i += 256)
            ((float4*)Gs)[i] = Gb[i];
        if (tid < Dd) {
            kss[tid] = g_v[bw*Dd + tid];
            b1s[tid] = b1[tid]; b2s[tid] = b2[tid];
            gms[tid] = gamma[tid]; bts[tid] = beta[tid];
        }
    }
    __syncthreads();

    // GEMM1: u = F @ G, column-packed (acc2[i][p] = row i, cols 2p,2p+1);
    // deg = F @ v fused as 4 scalar FFMA chains.
    unsigned long long acc2[4][2];
    #pragma unroll
    for (int i = 0; i < 4; ++i) { acc2[i][0] = 0ull; acc2[i][1] = 0ull; }
    float dg[4] = {0.f, 0.f, 0.f, 0.f};

    #pragma unroll 8
    for (int k = 0; k < 64; ++k) {
        const float4 a4 = *(const float4*)&QR[k*QPAD + ty*4];
        const float4 b4 = *(const float4*)&Gs[k*Dd + tx*4];
        const float  vk = kss[k];
        const unsigned long long b01 = pk2(b4.x, b4.y);   // register pair
        const unsigned long long b23 = pk2(b4.z, b4.w);   // register pair
        const float av[4] = {a4.x, a4.y, a4.z, a4.w};
        #pragma unroll
        for (int i = 0; i < 4; ++i) {
            const unsigned long long ad = pk2(av[i], av[i]);
            fma2(acc2[i][0], ad, b01);
            fma2(acc2[i][1], ad, b23);
            dg[i] += av[i] * vk;
        }
    }

    float acc[4][4];
    #pragma unroll
    for (int i = 0; i < 4; ++i) {
        unpk2(acc2[i][0], acc[i][0], acc[i][1]);
        unpk2(acc2[i][1], acc[i][2], acc[i][3]);
    }

    // relu(u/deg + b1) -> registers
    float r[4][4];
    #pragma unroll
    for (int i = 0; i < 4; ++i) {
        const float dinv = (dg[i] == 0.0f) ? 0.0f : 1.0f / dg[i];
        #pragma unroll
        for (int j = 0; j < 4; ++j)
            r[i][j] = fmaxf(acc[i][j] * dinv + b1s[tx*4 + j], 0.0f);
    }
    __syncthreads();   // everyone done reading QR/Gs

    // store R^T as float4 columns; load w2 global -> Gs (L2-hot)
    #pragma unroll
    for (int j = 0; j < 4; ++j)
        *(float4*)&QR[(tx*4 + j)*QPAD + ty*4] =
            make_float4(r[0][j], r[1][j], r[2][j], r[3][j]);
    {
        const float4* w2b = (const float4*)w2;
        #pragma unroll
        for (int i = 0; i < 4; ++i)
            ((float4*)Gs)[tid + i*256] = w2b[tid + i*256];
    }
    __syncthreads();

    // GEMM2: h = R @ w2 (column-packed)
    #pragma unroll
    for (int i = 0; i < 4; ++i) { acc2[i][0] = 0ull; acc2[i][1] = 0ull; }

    #pragma unroll 8
    for (int k = 0; k < 64; ++k) {
        const float4 a4 = *(const float4*)&QR[k*QPAD + ty*4];
        const float4 b4 = *(const float4*)&Gs[k*Dd + tx*4];
        const unsigned long long b01 = pk2(b4.x, b4.y);
        const unsigned long long b23 = pk2(b4.z, b4.w);
        const float av[4] = {a4.x, a4.y, a4.z, a4.w};
        #pragma unroll
        for (int i = 0; i < 4; ++i) {
            const unsigned long long ad = pk2(av[i], av[i]);
            fma2(acc2[i][0], ad, b01);
            fma2(acc2[i][1], ad, b23);
        }
    }
    #pragma unroll
    for (int i = 0; i < 4; ++i) {
        unpk2(acc2[i][0], acc[i][0], acc[i][1]);
        unpk2(acc2[i][1], acc[i][2], acc[i][3]);
    }

    // epilogue: residual + bias, LayerNorm per row (16 threads/row, width-16 shfl)
    float* ob = out + ((size_t)bw * Nn + r0) * Dd;
    #pragma unroll
    for (int i = 0; i < 4; ++i) {
        const int row = ty*4 + i;
        const bool valid = row < nr;
        float4 f4 = make_float4(0.f, 0.f, 0.f, 0.f);
        if (valid) f4 = ((const float4*)fb)[row*16 + tx];
        float h0 = acc[i][0] + f4.x + b2s[tx*4 + 0];
        float h1 = acc[i][1] + f4.y + b2s[tx*4 + 1];
        float h2 = acc[i][2] + f4.z + b2s[tx*4 + 2];
        float h3 = acc[i][3] + f4.w + b2s[tx*4 + 3];

        float s = h0 + h1 + h2 + h3;
        #pragma unroll
        for (int m = 1; m < 16; m <<= 1)
            s += __shfl_xor_sync(0xffffffffu, s, m, 16);
        const float mu = s * (1.0f / 64.0f);

        float a0 = h0 - mu, a1 = h1 - mu, a2 = h2 - mu, a3 = h3 - mu;
        float vs = a0*a0 + a1*a1 + a2*a2 + a3*a3;
        #pragma unroll
        for (int m = 1; m < 16; m <<= 1)
            vs += __shfl_xor_sync(0xffffffffu, vs, m, 16);
        const float rstd = rsqrtf(vs * (1.0f / 64.0f) + 1e-5f);

        if (valid) {
            float4 o;
            o.x = a0 * rstd * gms[tx*4 + 0] + bts[tx*4 + 0];
            o.y = a1 * rstd * gms[tx*4 + 1] + bts[tx*4 + 1];
            o.z = a2 * rstd * gms[tx*4 + 2] + bts[tx*4 + 2];
            o.w = a3 * rstd * gms[tx*4 + 3] + bts[tx*4 + 3];
            ((float4*)ob)[row*16 + tx] = o;
        }
    }
}

extern "C" void kernel_launch(void* const* d_in, const int* in_sizes, int n_in,
                              void* d_out, int out_size) {
    const float* feat    = (const float*)d_in[0];
    const float* weights = (const float*)d_in[1];
    const float* w1      = (const float*)d_in[2];
    const float* b1      = (const float*)d_in[3];
    const float* w2      = (const float*)d_in[4];
    const float* b2      = (const float*)d_in[5];
    const float* gamma   = (const float*)d_in[6];
    const float* beta    = (const float*)d_in[7];
    float* out = (float*)d_out;

    kA<<<BT*5, 256>>>(feat, weights);
    kB<<<BW, 256>>>(w1, weights);
    kC<<<BW*5, 256>>>(feat, b1, w2, b2, gamma, beta, out);
}

// round 15
// speedup vs baseline: 1.0362x; 1.0121x over previous
#include <cuda_runtime.h>
#include <math.h>

#define Bb 16
#define Tt 12
#define Nn 300
#define Dd 64
#define T2 10
#define BT (Bb*Tt)        // 192
#define BW (Bb*T2)        // 160
#define QPAD 68           // padded row stride (multiple of 4 for float4 LDS)

// dynamic smem layout for kC (floats)
#define OFF_GS   0
#define OFF_WS   4096
#define OFF_QR   8192
#define OFF_RT   (8192 + 64*QPAD)
#define OFF_KSS  (OFF_RT + 64*QPAD)
#define OFF_B1   (OFF_KSS + 64)
#define OFF_B2   (OFF_B1 + 64)
#define OFF_GM   (OFF_B2 + 64)
#define OFF_BT   (OFF_GM + 64)
#define KC_SMEM_FLOATS (OFF_BT + 64)
#define KC_SMEM_BYTES  (KC_SMEM_FLOATS * 4)

// Scratch (static device allocations; no cudaMalloc allowed)
__device__ float g_S5[BT*5*Dd*Dd];     // partial S = sum_n sc_n f f^T per (bt,chunk)
__device__ float g_ss5[BT*5*Dd];       // partial ss = sum_n sc_n f[n,:]
__device__ float g_G[BW*Dd*Dd];        // per-window diag(sw^2) S_win w1
__device__ float g_v[BW*Dd];           // per-window sw^2 * ss_win

// ---- packed f32x2 helpers (sm_103a) ---------------------------------------
__device__ __forceinline__ unsigned long long pk2(float lo, float hi) {
    unsigned long long r;
    asm("mov.b64 %0, {%1, %2};" : "=l"(r) : "f"(lo), "f"(hi));
    return r;
}
__device__ __forceinline__ void unpk2(unsigned long long v, float& lo, float& hi) {
    asm("mov.b64 {%0, %1}, %2;" : "=f"(lo), "=f"(hi) : "l"(v));
}
__device__ __forceinline__ unsigned long long mul2(unsigned long long a,
                                                   unsigned long long b) {
    unsigned long long r;
    asm("mul.rn.f32x2 %0, %1, %2;" : "=l"(r) : "l"(a), "l"(b));
    return r;
}
__device__ __forceinline__ void fma2(unsigned long long& d,
                                     unsigned long long a,
                                     unsigned long long b) {
    asm("fma.rn.f32x2 %0, %1, %2, %0;" : "+l"(d) : "l"(a), "l"(b));
}

// ---------------------------------------------------------------------------
// Kernel A (R10-proven, frozen): per (bt, chunk of <=64 rows):
//   sc_n = 1/max(||f_n .* sw||,eps); partial S (symmetric, upper-tri 4x4
//   tiles mirrored); partial ss. 256 threads, norm fused into staging.
// ---------------------------------------------------------------------------
__global__ __launch_bounds__(256) void kA(const float* __restrict__ feat,
                                          const float* __restrict__ weights) {
    __shared__ float fs[64][Dd];
    __shared__ float scs[64];
    const int blk = blockIdx.x;
    const int bt  = blk / 5;
    const int c   = blk % 5;
    const int r0  = c * 64;
    const int nr  = min(64, Nn - r0);     // 64 or 44
    const int tid = threadIdx.x;
    const int c4  = tid & 15;             // float4 slot within a row

    float4 swv;
    swv.x = 1.0f / (1.0f + expf(-weights[c4*4 + 0]));
    swv.y = 1.0f / (1.0f + expf(-weights[c4*4 + 1]));
    swv.z = 1.0f / (1.0f + expf(-weights[c4*4 + 2]));
    swv.w = 1.0f / (1.0f + expf(-weights[c4*4 + 3]));

    const float* fbase = feat + ((size_t)bt * Nn + r0) * Dd;
    const int nv   = nr * 16;                 // float4 count
    const int trip = ((nv + 255) & ~255);     // uniform trip count for shfl

    for (int i = tid; i < trip; i += 256) {
        float4 v = make_float4(0.f, 0.f, 0.f, 0.f);
        const bool ok = i < nv;
        if (ok) v = ((const float4*)fbase)[i];
        const float px = v.x*swv.x, py = v.y*swv.y;
        const float pz = v.z*swv.z, pw = v.w*swv.w;
        float ps = px*px + py*py + pz*pz + pw*pw;
        ps += __shfl_xor_sync(0xffffffffu, ps, 1, 16);
        ps += __shfl_xor_sync(0xffffffffu, ps, 2, 16);
        ps += __shfl_xor_sync(0xffffffffu, ps, 4, 16);
        ps += __shfl_xor_sync(0xffffffffu, ps, 8, 16);
        if (ok) {
            ((float4*)fs)[i] = v;
            if (c4 == 0)
                scs[i >> 4] = 1.0f / fmaxf(sqrtf(ps), 1e-12f);
        }
    }
    __syncthreads();

    if (tid < 136) {
        int t = tid, rr = 0;
        while (t >= 16 - rr) { t -= 16 - rr; ++rr; }
        const int cc = rr + t;

        unsigned long long acc2[2][4];
        #pragma unroll
        for (int p = 0; p < 2; ++p)
            #pragma unroll
            for (int d = 0; d < 4; ++d) acc2[p][d] = 0ull;

        #pragma unroll 8
        for (int n = 0; n < nr; ++n) {
            const float  sc = scs[n];
            const float4 w4 = *(const float4*)&fs[n][rr*4];
            const float4 f4 = *(const float4*)&fs[n][cc*4];
            const unsigned long long scp = pk2(sc, sc);
            const unsigned long long sv01 = mul2(scp, pk2(w4.x, w4.y));
            const unsigned long long sv23 = mul2(scp, pk2(w4.z, w4.w));
            const float fv[4] = {f4.x, f4.y, f4.z, f4.w};
            #pragma unroll
            for (int d = 0; d < 4; ++d) {
                const unsigned long long fdd = pk2(fv[d], fv[d]);
                fma2(acc2[0][d], sv01, fdd);
                fma2(acc2[1][d], sv23, fdd);
            }
        }

        float acc[4][4];
        #pragma unroll
        for (int d = 0; d < 4; ++d) {
            unpk2(acc2[0][d], acc[0][d], acc[1][d]);
            unpk2(acc2[1][d], acc[2][d], acc[3][d]);
        }

        float* Sb = g_S5 + (size_t)blk * Dd * Dd;
        #pragma unroll
        for (int jj = 0; jj < 4; ++jj)
            *(float4*)&Sb[(rr*4 + jj)*Dd + cc*4] =
                make_float4(acc[jj][0], acc[jj][1], acc[jj][2], acc[jj][3]);
        if (rr != cc) {
            #pragma unroll
            for (int dd = 0; dd < 4; ++dd)
                *(float4*)&Sb[(cc*4 + dd)*Dd + rr*4] =
                    make_float4(acc[0][dd], acc[1][dd], acc[2][dd], acc[3][dd]);
        }
    } else if (tid >= 224 && tid < 240) {
        const int jg = tid - 224;
        float ksa[4] = {0.f, 0.f, 0.f, 0.f};
        #pragma unroll 4
        for (int n = 0; n < nr; ++n) {
            const float  sc = scs[n];
            const float4 w4 = *(const float4*)&fs[n][jg*4];
            ksa[0] += sc*w4.x; ksa[1] += sc*w4.y;
            ksa[2] += sc*w4.z; ksa[3] += sc*w4.w;
        }
        *(float4*)&g_ss5[blk*Dd + jg*4] =
            make_float4(ksa[0], ksa[1], ksa[2], ksa[3]);
    }
}

// ---------------------------------------------------------------------------
// Kernel B (frozen): per window: Ms[j,:] = sw2[j] * sum of 15 partial S;
//   G = Ms @ w1;  v[j] = sw2[j] * sum of 15 partial ss. grid=160, 256 thr.
// ---------------------------------------------------------------------------
__global__ __launch_bounds__(256) void kB(const float* __restrict__ w1,
                                          const float* __restrict__ weights) {
    __shared__ float Ms[Dd*Dd];
    __shared__ float w1s[Dd*Dd];
    __shared__ float sw2[Dd];
    const int bw  = blockIdx.x;
    const int b   = bw / T2;
    const int t2  = bw % T2;
    const int bt0 = b * Tt + t2;
    const int tid = threadIdx.x;

    if (tid < Dd) {
        float s = 1.0f / (1.0f + expf(-weights[tid]));
        sw2[tid] = s * s;
    }
    __syncthreads();

    for (int i = tid; i < 1024; i += 256) {
        float4 m = make_float4(0.f, 0.f, 0.f, 0.f);
        #pragma unroll
        for (int s = 0; s < 3; ++s)
            #pragma unroll
            for (int cc = 0; cc < 5; ++cc) {
                const float4 v = ((const float4*)(g_S5 +
                    (size_t)((bt0 + s)*5 + cc) * Dd * Dd))[i];
                m.x += v.x; m.y += v.y; m.z += v.z; m.w += v.w;
            }
        const float s2 = sw2[i >> 4];
        m.x *= s2; m.y *= s2; m.z *= s2; m.w *= s2;
        ((float4*)Ms)[i]  = m;
        ((float4*)w1s)[i] = ((const float4*)w1)[i];
    }
    if (tid < Dd) {
        float s = 0.0f;
        #pragma unroll
        for (int sl = 0; sl < 15; ++sl)
            s += g_ss5[((bt0 + sl/5)*5 + sl%5)*Dd + tid];
        g_v[bw*Dd + tid] = sw2[tid] * s;
    }
    __syncthreads();

    const int d  = tid & 63;
    const int jg = tid >> 6;
    float* Gb = g_G + (size_t)bw * Dd * Dd;
    for (int j = jg*16; j < jg*16 + 16; ++j) {
        float s = 0.0f;
        #pragma unroll 16
        for (int k = 0; k < 64; ++k)
            s += Ms[j*64 + k] * w1s[k*64 + d];
        Gb[j*64 + d] = s;
    }
}

// ---------------------------------------------------------------------------
// Kernel C (restructured): per (window, 64-row tile).
// Dynamic smem: Gs | Ws(w2, cp.async) | QR(F^T) | RT(R^T) | vectors.
// Two barriers total; w2 load overlaps GEMM1 via cp.async.
// ---------------------------------------------------------------------------
__global__ __launch_bounds__(256, 3) void kC(const float* __restrict__ feat,
                                             const float* __restrict__ b1,
                                             const float* __restrict__ w2,
                                             const float* __restrict__ b2,
                                             const float* __restrict__ gamma,
                                             const float* __restrict__ beta,
                                             float* __restrict__ out) {
    extern __shared__ float sm[];
    float* Gs  = sm + OFF_GS;
    float* Ws  = sm + OFF_WS;
    float* QR  = sm + OFF_QR;
    float* RT  = sm + OFF_RT;
    float* kss = sm + OFF_KSS;
    float* b1s = sm + OFF_B1;
    float* b2s = sm + OFF_B2;
    float* gms = sm + OFF_GM;
    float* bts = sm + OFF_BT;

    const int blk  = blockIdx.x;
    const int bw   = blk / 5;
    const int tile = blk % 5;
    const int r0   = tile * 64;
    const int nr   = min(64, Nn - r0);
    const int b    = bw / T2;
    const int t2   = bw % T2;
    const int tid  = threadIdx.x;
    const int ty   = tid >> 4;       // row group 0..15
    const int tx   = tid & 15;       // col group 0..15

    const float* fb = feat + ((size_t)((b*Tt + t2 + 2)*Nn) + r0) * Dd;

    // cp.async: prefetch w2 into Ws (overlaps everything up to GEMM2)
    {
        unsigned int ws_addr = (unsigned int)__cvta_generic_to_shared(Ws);
        #pragma unroll
        for (int i = 0; i < 4; ++i) {
            const unsigned int dst = ws_addr + (tid + i*256) * 16;
            const float4* src = ((const float4*)w2) + tid + i*256;
            asm volatile("cp.async.cg.shared.global [%0], [%1], 16;"
                         :: "r"(dst), "l"(src));
        }
        asm volatile("cp.async.commit_group;");
    }

    // stage F^T (zero-fill invalid rows), G, small vectors
    {
        const float4* qb = (const float4*)fb;
        for (int idx = tid; idx < 1024; idx += 256) {
            const int row = idx >> 4, c4 = idx & 15;
            float4 v = make_float4(0.f, 0.f, 0.f, 0.f);
            if (row < nr) v = qb[row*16 + c4];
            QR[(c4*4 + 0)*QPAD + row] = v.x;
            QR[(c4*4 + 1)*QPAD + row] = v.y;
            QR[(c4*4 + 2)*QPAD + row] = v.z;
            QR[(c4*4 + 3)*QPAD + row] = v.w;
        }
        const float4* Gb = (const float4*)(g_G + (size_t)bw * Dd * Dd);
        for (int i = tid; i < 1024; i += 256)
            ((float4*)Gs)[i] = Gb[i];
        if (tid < Dd) {
            kss[tid] = g_v[bw*Dd + tid];
            b1s[tid] = b1[tid]; b2s[tid] = b2[tid];
            gms[tid] = gamma[tid]; bts[tid] = beta[tid];
        }
    }
    __syncthreads();                 // barrier 1

    // GEMM1: u = F @ G, column-packed; deg = F @ v fused.
    unsigned long long acc2[4][2];
    #pragma unroll
    for (int i = 0; i < 4; ++i) { acc2[i][0] = 0ull; acc2[i][1] = 0ull; }
    float dg[4] = {0.f, 0.f, 0.f, 0.f};

    #pragma unroll 8
    for (int k = 0; k < 64; ++k) {
        const float4 a4 = *(const float4*)&QR[k*QPAD + ty*4];
        const float4 b4 = *(const float4*)&Gs[k*Dd + tx*4];
        const float  vk = kss[k];
        const unsigned long long b01 = pk2(b4.x, b4.y);
        const unsigned long long b23 = pk2(b4.z, b4.w);
        const float av[4] = {a4.x, a4.y, a4.z, a4.w};
        #pragma unroll
        for (int i = 0; i < 4; ++i) {
            const unsigned long long ad = pk2(av[i], av[i]);
            fma2(acc2[i][0], ad, b01);
            fma2(acc2[i][1], ad, b23);
            dg[i] += av[i] * vk;
        }
    }

    float acc[4][4];
    #pragma unroll
    for (int i = 0; i < 4; ++i) {
        unpk2(acc2[i][0], acc[i][0], acc[i][1]);
        unpk2(acc2[i][1], acc[i][2], acc[i][3]);
    }

    // relu(u/deg + b1) and write R^T into its own buffer (no hazard)
    #pragma unroll
    for (int i = 0; i < 4; ++i) {
        const float dinv = (dg[i] == 0.0f) ? 0.0f : 1.0f / dg[i];
        #pragma unroll
        for (int j = 0; j < 4; ++j)
            acc[i][j] = fmaxf(acc[i][j] * dinv + b1s[tx*4 + j], 0.0f);
    }
    #pragma unroll
    for (int j = 0; j < 4; ++j)
        *(float4*)&RT[(tx*4 + j)*QPAD + ty*4] =
            make_float4(acc[0][j], acc[1][j], acc[2][j], acc[3][j]);

    asm volatile("cp.async.wait_group 0;" ::: "memory");
    __syncthreads();                 // barrier 2 (RT ready + Ws visible)

    // GEMM2: h = R @ w2 (column-packed)
    #pragma unroll
    for (int i = 0; i < 4; ++i) { acc2[i][0] = 0ull; acc2[i][1] = 0ull; }

    #pragma unroll 8
    for (int k = 0; k < 64; ++k) {
        const float4 a4 = *(const float4*)&RT[k*QPAD + ty*4];
        const float4 b4 = *(const float4*)&Ws[k*Dd + tx*4];
        const unsigned long long b01 = pk2(b4.x, b4.y);
        const unsigned long long b23 = pk2(b4.z, b4.w);
        const float av[4] = {a4.x, a4.y, a4.z, a4.w};
        #pragma unroll
        for (int i = 0; i < 4; ++i) {
            const unsigned long long ad = pk2(av[i], av[i]);
            fma2(acc2[i][0], ad, b01);
            fma2(acc2[i][1], ad, b23);
        }
    }
    #pragma unroll
    for (int i = 0; i < 4; ++i) {
        unpk2(acc2[i][0], acc[i][0], acc[i][1]);
        unpk2(acc2[i][1], acc[i][2], acc[i][3]);
    }

    // epilogue: residual + bias, LayerNorm per row (16 threads/row)
    float* ob = out + ((size_t)bw * Nn + r0) * Dd;
    #pragma unroll
    for (int i = 0; i < 4; ++i) {
        const int row = ty*4 + i;
        const bool valid = row < nr;
        float4 f4 = make_float4(0.f, 0.f, 0.f, 0.f);
        if (valid) f4 = ((const float4*)fb)[row*16 + tx];
        float h0 = acc[i][0] + f4.x + b2s[tx*4 + 0];
        float h1 = acc[i][1] + f4.y + b2s[tx*4 + 1];
        float h2 = acc[i][2] + f4.z + b2s[tx*4 + 2];
        float h3 = acc[i][3] + f4.w + b2s[tx*4 + 3];

        float s = h0 + h1 + h2 + h3;
        #pragma unroll
        for (int m = 1; m < 16; m <<= 1)
            s += __shfl_xor_sync(0xffffffffu, s, m, 16);
        const float mu = s * (1.0f / 64.0f);

        float a0 = h0 - mu, a1 = h1 - mu, a2 = h2 - mu, a3 = h3 - mu;
        float vs = a0*a0 + a1*a1 + a2*a2 + a3*a3;
        #pragma unroll
        for (int m = 1; m < 16; m <<= 1)
            vs += __shfl_xor_sync(0xffffffffu, vs, m, 16);
        const float rstd = rsqrtf(vs * (1.0f / 64.0f) + 1e-5f);

        if (valid) {
            float4 o;
            o.x = a0 * rstd * gms[tx*4 + 0] + bts[tx*4 + 0];
            o.y = a1 * rstd * gms[tx*4 + 1] + bts[tx*4 + 1];
            o.z = a2 * rstd * gms[tx*4 + 2] + bts[tx*4 + 2];
            o.w = a3 * rstd * gms[tx*4 + 3] + bts[tx*4 + 3];
            ((float4*)ob)[row*16 + tx] = o;
        }
    }
}

extern "C" void kernel_launch(void* const* d_in, const int* in_sizes, int n_in,
                              void* d_out, int out_size) {
    const float* feat    = (const float*)d_in[0];
    const float* weights = (const float*)d_in[1];
    const float* w1      = (const float*)d_in[2];
    const float* b1      = (const float*)d_in[3];
    const float* w2      = (const float*)d_in[4];
    const float* b2      = (const float*)d_in[5];
    const float* gamma   = (const float*)d_in[6];
    const float* beta    = (const float*)d_in[7];
    float* out = (float*)d_out;

    // idempotent, host-side, non-allocating (needed for >48KB dynamic smem)
    cudaFuncSetAttribute(kC, cudaFuncAttributeMaxDynamicSharedMemorySize,
                         KC_SMEM_BYTES);

    kA<<<BT*5, 256>>>(feat, weights);
    kB<<<BW, 256>>>(w1, weights);
    kC<<<BW*5, 256, KC_SMEM_BYTES>>>(feat, b1, w2, b2, gamma, beta, out);
}

// round 16
// speedup vs baseline: 1.2032x; 1.1612x over previous
#include <cuda_runtime.h>
#include <math.h>

#define Bb 16
#define Tt 12
#define Nn 300
#define Dd 64
#define T2 10
#define BT (Bb*Tt)        // 192
#define BW (Bb*T2)        // 160
#define QPAD 68           // padded row stride (multiple of 4 for float4 LDS)

// dynamic smem layout for kC (floats)
#define OFF_GS   0
#define OFF_WS   4096
#define OFF_QR   8192
#define OFF_RT   (8192 + 64*QPAD)
#define OFF_KSS  (OFF_RT + 64*QPAD)
#define OFF_B1   (OFF_KSS + 64)
#define OFF_B2   (OFF_B1 + 64)
#define OFF_GM   (OFF_B2 + 64)
#define OFF_BT   (OFF_GM + 64)
#define KC_SMEM_FLOATS (OFF_BT + 64)
#define KC_SMEM_BYTES  (KC_SMEM_FLOATS * 4)

// Scratch (static device allocations; no cudaMalloc allowed)
__device__ float g_S5[BT*5*Dd*Dd];     // partial S = sum_n sc_n f f^T per (bt,chunk)
__device__ float g_ss5[BT*5*Dd];       // partial ss = sum_n sc_n f[n,:]
__device__ float g_G[BW*Dd*Dd];        // per-window diag(sw^2) S_win w1
__device__ float g_v[BW*Dd];           // per-window sw^2 * ss_win

// ---- packed f32x2 helpers (sm_103a) ---------------------------------------
__device__ __forceinline__ unsigned long long pk2(float lo, float hi) {
    unsigned long long r;
    asm("mov.b64 %0, {%1, %2};" : "=l"(r) : "f"(lo), "f"(hi));
    return r;
}
__device__ __forceinline__ void unpk2(unsigned long long v, float& lo, float& hi) {
    asm("mov.b64 {%0, %1}, %2;" : "=f"(lo), "=f"(hi) : "l"(v));
}
__device__ __forceinline__ unsigned long long mul2(unsigned long long a,
                                                   unsigned long long b) {
    unsigned long long r;
    asm("mul.rn.f32x2 %0, %1, %2;" : "=l"(r) : "l"(a), "l"(b));
    return r;
}
__device__ __forceinline__ void fma2(unsigned long long& d,
                                     unsigned long long a,
                                     unsigned long long b) {
    asm("fma.rn.f32x2 %0, %1, %2, %0;" : "+l"(d) : "l"(a), "l"(b));
}

// ---------------------------------------------------------------------------
// Kernel A (R10-proven, frozen): per (bt, chunk of <=64 rows):
//   sc_n = 1/max(||f_n .* sw||,eps); partial S (symmetric, upper-tri 4x4
//   tiles mirrored); partial ss. 256 threads, norm fused into staging.
// ---------------------------------------------------------------------------
__global__ __launch_bounds__(256) void kA(const float* __restrict__ feat,
                                          const float* __restrict__ weights) {
    __shared__ float fs[64][Dd];
    __shared__ float scs[64];
    const int blk = blockIdx.x;
    const int bt  = blk / 5;
    const int c   = blk % 5;
    const int r0  = c * 64;
    const int nr  = min(64, Nn - r0);     // 64 or 44
    const int tid = threadIdx.x;
    const int c4  = tid & 15;             // float4 slot within a row

    float4 swv;
    swv.x = 1.0f / (1.0f + expf(-weights[c4*4 + 0]));
    swv.y = 1.0f / (1.0f + expf(-weights[c4*4 + 1]));
    swv.z = 1.0f / (1.0f + expf(-weights[c4*4 + 2]));
    swv.w = 1.0f / (1.0f + expf(-weights[c4*4 + 3]));

    const float* fbase = feat + ((size_t)bt * Nn + r0) * Dd;
    const int nv   = nr * 16;                 // float4 count
    const int trip = ((nv + 255) & ~255);     // uniform trip count for shfl

    for (int i = tid; i < trip; i += 256) {
        float4 v = make_float4(0.f, 0.f, 0.f, 0.f);
        const bool ok = i < nv;
        if (ok) v = ((const float4*)fbase)[i];
        const float px = v.x*swv.x, py = v.y*swv.y;
        const float pz = v.z*swv.z, pw = v.w*swv.w;
        float ps = px*px + py*py + pz*pz + pw*pw;
        ps += __shfl_xor_sync(0xffffffffu, ps, 1, 16);
        ps += __shfl_xor_sync(0xffffffffu, ps, 2, 16);
        ps += __shfl_xor_sync(0xffffffffu, ps, 4, 16);
        ps += __shfl_xor_sync(0xffffffffu, ps, 8, 16);
        if (ok) {
            ((float4*)fs)[i] = v;
            if (c4 == 0)
                scs[i >> 4] = 1.0f / fmaxf(sqrtf(ps), 1e-12f);
        }
    }
    __syncthreads();

    if (tid < 136) {
        int t = tid, rr = 0;
        while (t >= 16 - rr) { t -= 16 - rr; ++rr; }
        const int cc = rr + t;

        unsigned long long acc2[2][4];
        #pragma unroll
        for (int p = 0; p < 2; ++p)
            #pragma unroll
            for (int d = 0; d < 4; ++d) acc2[p][d] = 0ull;

        #pragma unroll 8
        for (int n = 0; n < nr; ++n) {
            const float  sc = scs[n];
            const float4 w4 = *(const float4*)&fs[n][rr*4];
            const float4 f4 = *(const float4*)&fs[n][cc*4];
            const unsigned long long scp = pk2(sc, sc);
            const unsigned long long sv01 = mul2(scp, pk2(w4.x, w4.y));
            const unsigned long long sv23 = mul2(scp, pk2(w4.z, w4.w));
            const float fv[4] = {f4.x, f4.y, f4.z, f4.w};
            #pragma unroll
            for (int d = 0; d < 4; ++d) {
                const unsigned long long fdd = pk2(fv[d], fv[d]);
                fma2(acc2[0][d], sv01, fdd);
                fma2(acc2[1][d], sv23, fdd);
            }
        }

        float acc[4][4];
        #pragma unroll
        for (int d = 0; d < 4; ++d) {
            unpk2(acc2[0][d], acc[0][d], acc[1][d]);
            unpk2(acc2[1][d], acc[2][d], acc[3][d]);
        }

        float* Sb = g_S5 + (size_t)blk * Dd * Dd;
        #pragma unroll
        for (int jj = 0; jj < 4; ++jj)
            *(float4*)&Sb[(rr*4 + jj)*Dd + cc*4] =
                make_float4(acc[jj][0], acc[jj][1], acc[jj][2], acc[jj][3]);
        if (rr != cc) {
            #pragma unroll
            for (int dd = 0; dd < 4; ++dd)
                *(float4*)&Sb[(cc*4 + dd)*Dd + rr*4] =
                    make_float4(acc[0][dd], acc[1][dd], acc[2][dd], acc[3][dd]);
        }
    } else if (tid >= 224 && tid < 240) {
        const int jg = tid - 224;
        float ksa[4] = {0.f, 0.f, 0.f, 0.f};
        #pragma unroll 4
        for (int n = 0; n < nr; ++n) {
            const float  sc = scs[n];
            const float4 w4 = *(const float4*)&fs[n][jg*4];
            ksa[0] += sc*w4.x; ksa[1] += sc*w4.y;
            ksa[2] += sc*w4.z; ksa[3] += sc*w4.w;
        }
        *(float4*)&g_ss5[blk*Dd + jg*4] =
            make_float4(ksa[0], ksa[1], ksa[2], ksa[3]);
    }
}

// ---------------------------------------------------------------------------
// Kernel B (rewritten GEMM): per window:
//   Ss = raw sum of 15 partial S slices (SYMMETRIC);
//   G[j][d] = sw2[j] * sum_k Ss[k][j] * w1[k][d]   (column read via symmetry
//   -> float4 a-side, 4x4 thread tiles, packed f32x2 like kC);
//   v[j] = sw2[j] * sum of 15 partial ss.  grid=160, 256 thr.
// ---------------------------------------------------------------------------
__global__ __launch_bounds__(256) void kB(const float* __restrict__ w1,
                                          const float* __restrict__ weights) {
    __shared__ float Ss[Dd*Dd];      // raw symmetric window sum
    __shared__ float w1s[Dd*Dd];
    __shared__ float sw2[Dd];
    const int bw  = blockIdx.x;
    const int b   = bw / T2;
    const int t2  = bw % T2;
    const int bt0 = b * Tt + t2;
    const int tid = threadIdx.x;

    if (tid < Dd) {
        float s = 1.0f / (1.0f + expf(-weights[tid]));
        sw2[tid] = s * s;
    }
    __syncthreads();

    for (int i = tid; i < 1024; i += 256) {
        float4 m = make_float4(0.f, 0.f, 0.f, 0.f);
        #pragma unroll
        for (int s = 0; s < 3; ++s)
            #pragma unroll
            for (int cc = 0; cc < 5; ++cc) {
                const float4 v = ((const float4*)(g_S5 +
                    (size_t)((bt0 + s)*5 + cc) * Dd * Dd))[i];
                m.x += v.x; m.y += v.y; m.z += v.z; m.w += v.w;
            }
        ((float4*)Ss)[i]  = m;                       // RAW (no sw2 here)
        ((float4*)w1s)[i] = ((const float4*)w1)[i];
    }
    if (tid < Dd) {
        float s = 0.0f;
        #pragma unroll
        for (int sl = 0; sl < 15; ++sl)
            s += g_ss5[((bt0 + sl/5)*5 + sl%5)*Dd + tid];
        g_v[bw*Dd + tid] = sw2[tid] * s;
    }
    __syncthreads();

    // G-GEMM, 4x4 thread tiles, column-packed f32x2.
    // a4 = Ss[k*64 + ty*4..] == S[j=ty*4..][k] by symmetry (broadcast LDS).
    const int ty = tid >> 4;
    const int tx = tid & 15;
    float s2v[4];
    #pragma unroll
    for (int i = 0; i < 4; ++i) s2v[i] = sw2[ty*4 + i];

    unsigned long long acc2[4][2];
    #pragma unroll
    for (int i = 0; i < 4; ++i) { acc2[i][0] = 0ull; acc2[i][1] = 0ull; }

    #pragma unroll 8
    for (int k = 0; k < 64; ++k) {
        const float4 a4 = *(const float4*)&Ss[k*Dd + ty*4];
        const float4 b4 = *(const float4*)&w1s[k*Dd + tx*4];
        const unsigned long long b01 = pk2(b4.x, b4.y);
        const unsigned long long b23 = pk2(b4.z, b4.w);
        const float av[4] = {a4.x, a4.y, a4.z, a4.w};
        #pragma unroll
        for (int i = 0; i < 4; ++i) {
            const unsigned long long ad = pk2(av[i], av[i]);
            fma2(acc2[i][0], ad, b01);
            fma2(acc2[i][1], ad, b23);
        }
    }

    float* Gb = g_G + (size_t)bw * Dd * Dd;
    #pragma unroll
    for (int i = 0; i < 4; ++i) {
        float g0, g1, g2, g3;
        unpk2(acc2[i][0], g0, g1);
        unpk2(acc2[i][1], g2, g3);
        *(float4*)&Gb[(ty*4 + i)*Dd + tx*4] =
            make_float4(g0*s2v[i], g1*s2v[i], g2*s2v[i], g3*s2v[i]);
    }
}

// ---------------------------------------------------------------------------
// Kernel C (frozen from R15): per (window, 64-row tile).
// Dynamic smem: Gs | Ws(w2, cp.async) | QR(F^T) | RT(R^T) | vectors.
// Two barriers; w2 load overlaps GEMM1 via cp.async.
// ---------------------------------------------------------------------------
__global__ __launch_bounds__(256, 3) void kC(const float* __restrict__ feat,
                                             const float* __restrict__ b1,
                                             const float* __restrict__ w2,
                                             const float* __restrict__ b2,
                                             const float* __restrict__ gamma,
                                             const float* __restrict__ beta,
                                             float* __restrict__ out) {
    extern __shared__ float sm[];
    float* Gs  = sm + OFF_GS;
    float* Ws  = sm + OFF_WS;
    float* QR  = sm + OFF_QR;
    float* RT  = sm + OFF_RT;
    float* kss = sm + OFF_KSS;
    float* b1s = sm + OFF_B1;
    float* b2s = sm + OFF_B2;
    float* gms = sm + OFF_GM;
    float* bts = sm + OFF_BT;

    const int blk  = blockIdx.x;
    const int bw   = blk / 5;
    const int tile = blk % 5;
    const int r0   = tile * 64;
    const int nr   = min(64, Nn - r0);
    const int b    = bw / T2;
    const int t2   = bw % T2;
    const int tid  = threadIdx.x;
    const int ty   = tid >> 4;       // row group 0..15
    const int tx   = tid & 15;       // col group 0..15

    const float* fb = feat + ((size_t)((b*Tt + t2 + 2)*Nn) + r0) * Dd;

    // cp.async: prefetch w2 into Ws (overlaps everything up to GEMM2)
    {
        unsigned int ws_addr = (unsigned int)__cvta_generic_to_shared(Ws);
        #pragma unroll
        for (int i = 0; i < 4; ++i) {
            const unsigned int dst = ws_addr + (tid + i*256) * 16;
            const float4* src = ((const float4*)w2) + tid + i*256;
            asm volatile("cp.async.cg.shared.global [%0], [%1], 16;"
                         :: "r"(dst), "l"(src));
        }
        asm volatile("cp.async.commit_group;");
    }

    // stage F^T (zero-fill invalid rows), G, small vectors
    {
        const float4* qb = (const float4*)fb;
        for (int idx = tid; idx < 1024; idx += 256) {
            const int row = idx >> 4, c4 = idx & 15;
            float4 v = make_float4(0.f, 0.f, 0.f, 0.f);
            if (row < nr) v = qb[row*16 + c4];
            QR[(c4*4 + 0)*QPAD + row] = v.x;
            QR[(c4*4 + 1)*QPAD + row] = v.y;
            QR[(c4*4 + 2)*QPAD + row] = v.z;
            QR[(c4*4 + 3)*QPAD + row] = v.w;
        }
        const float4* Gb = (const float4*)(g_G + (size_t)bw * Dd * Dd);
        for (int i = tid; i < 1024; i += 256)
            ((float4*)Gs)[i] = Gb[i];
        if (tid < Dd) {
            kss[tid] = g_v[bw*Dd + tid];
            b1s[tid] = b1[tid]; b2s[tid] = b2[tid];
            gms[tid] = gamma[tid]; bts[tid] = beta[tid];
        }
    }
    __syncthreads();                 // barrier 1

    // GEMM1: u = F @ G, column-packed; deg = F @ v fused.
    unsigned long long acc2[4][2];
    #pragma unroll
    for (int i = 0; i < 4; ++i) { acc2[i][0] = 0ull; acc2[i][1] = 0ull; }
    float dg[4] = {0.f, 0.f, 0.f, 0.f};

    #pragma unroll 8
    for (int k = 0; k < 64; ++k) {
        const float4 a4 = *(const float4*)&QR[k*QPAD + ty*4];
        const float4 b4 = *(const float4*)&Gs[k*Dd + tx*4];
        const float  vk = kss[k];
        const unsigned long long b01 = pk2(b4.x, b4.y);
        const unsigned long long b23 = pk2(b4.z, b4.w);
        const float av[4] = {a4.x, a4.y, a4.z, a4.w};
        #pragma unroll
        for (int i = 0; i < 4; ++i) {
            const unsigned long long ad = pk2(av[i], av[i]);
            fma2(acc2[i][0], ad, b01);
            fma2(acc2[i][1], ad, b23);
            dg[i] += av[i] * vk;
        }
    }

    float acc[4][4];
    #pragma unroll
    for (int i = 0; i < 4; ++i) {
        unpk2(acc2[i][0], acc[i][0], acc[i][1]);
        unpk2(acc2[i][1], acc[i][2], acc[i][3]);
    }

    // relu(u/deg + b1) and write R^T into its own buffer (no hazard)
    #pragma unroll
    for (int i = 0; i < 4; ++i) {
        const float dinv = (dg[i] == 0.0f) ? 0.0f : 1.0f / dg[i];
        #pragma unroll
        for (int j = 0; j < 4; ++j)
            acc[i][j] = fmaxf(acc[i][j] * dinv + b1s[tx*4 + j], 0.0f);
    }
    #pragma unroll
    for (int j = 0; j < 4; ++j)
        *(float4*)&RT[(tx*4 + j)*QPAD + ty*4] =
            make_float4(acc[0][j], acc[1][j], acc[2][j], acc[3][j]);

    asm volatile("cp.async.wait_group 0;" ::: "memory");
    __syncthreads();                 // barrier 2 (RT ready + Ws visible)

    // GEMM2: h = R @ w2 (column-packed)
    #pragma unroll
    for (int i = 0; i < 4; ++i) { acc2[i][0] = 0ull; acc2[i][1] = 0ull; }

    #pragma unroll 8
    for (int k = 0; k < 64; ++k) {
        const float4 a4 = *(const float4*)&RT[k*QPAD + ty*4];
        const float4 b4 = *(const float4*)&Ws[k*Dd + tx*4];
        const unsigned long long b01 = pk2(b4.x, b4.y);
        const unsigned long long b23 = pk2(b4.z, b4.w);
        const float av[4] = {a4.x, a4.y, a4.z, a4.w};
        #pragma unroll
        for (int i = 0; i < 4; ++i) {
            const unsigned long long ad = pk2(av[i], av[i]);
            fma2(acc2[i][0], ad, b01);
            fma2(acc2[i][1], ad, b23);
        }
    }
    #pragma unroll
    for (int i = 0; i < 4; ++i) {
        unpk2(acc2[i][0], acc[i][0], acc[i][1]);
        unpk2(acc2[i][1], acc[i][2], acc[i][3]);
    }

    // epilogue: residual + bias, LayerNorm per row (16 threads/row)
    float* ob = out + ((size_t)bw * Nn + r0) * Dd;
    #pragma unroll
    for (int i = 0; i < 4; ++i) {
        const int row = ty*4 + i;
        const bool valid = row < nr;
        float4 f4 = make_float4(0.f, 0.f, 0.f, 0.f);
        if (valid) f4 = ((const float4*)fb)[row*16 + tx];
        float h0 = acc[i][0] + f4.x + b2s[tx*4 + 0];
        float h1 = acc[i][1] + f4.y + b2s[tx*4 + 1];
        float h2 = acc[i][2] + f4.z + b2s[tx*4 + 2];
        float h3 = acc[i][3] + f4.w + b2s[tx*4 + 3];

        float s = h0 + h1 + h2 + h3;
        #pragma unroll
        for (int m = 1; m < 16; m <<= 1)
            s += __shfl_xor_sync(0xffffffffu, s, m, 16);
        const float mu = s * (1.0f / 64.0f);

        float a0 = h0 - mu, a1 = h1 - mu, a2 = h2 - mu, a3 = h3 - mu;
        float vs = a0*a0 + a1*a1 + a2*a2 + a3*a3;
        #pragma unroll
        for (int m = 1; m < 16; m <<= 1)
            vs += __shfl_xor_sync(0xffffffffu, vs, m, 16);
        const float rstd = rsqrtf(vs * (1.0f / 64.0f) + 1e-5f);

        if (valid) {
            float4 o;
            o.x = a0 * rstd * gms[tx*4 + 0] + bts[tx*4 + 0];
            o.y = a1 * rstd * gms[tx*4 + 1] + bts[tx*4 + 1];
            o.z = a2 * rstd * gms[tx*4 + 2] + bts[tx*4 + 2];
            o.w = a3 * rstd * gms[tx*4 + 3] + bts[tx*4 + 3];
            ((float4*)ob)[row*16 + tx] = o;
        }
    }
}

extern "C" void kernel_launch(void* const* d_in, const int* in_sizes, int n_in,
                              void* d_out, int out_size) {
    const float* feat    = (const float*)d_in[0];
    const float* weights = (const float*)d_in[1];
    const float* w1      = (const float*)d_in[2];
    const float* b1      = (const float*)d_in[3];
    const float* w2      = (const float*)d_in[4];
    const float* b2      = (const float*)d_in[5];
    const float* gamma   = (const float*)d_in[6];
    const float* beta    = (const float*)d_in[7];
    float* out = (float*)d_out;

    // idempotent, host-side, non-allocating (needed for >48KB dynamic smem)
    cudaFuncSetAttribute(kC, cudaFuncAttributeMaxDynamicSharedMemorySize,
                         KC_SMEM_BYTES);

    kA<<<BT*5, 256>>>(feat, weights);
    kB<<<BW, 256>>>(w1, weights);
    kC<<<BW*5, 256, KC_SMEM_BYTES>>>(feat, b1, w2, b2, gamma, beta, out);
}

// round 17
// speedup vs baseline: 1.2385x; 1.0294x over previous
#include <cuda_runtime.h>
#include <math.h>

#define Bb 16
#define Tt 12
#define Nn 300
#define Dd 64
#define T2 10
#define BT (Bb*Tt)        // 192
#define BW (Bb*T2)        // 160
#define QPAD 68           // padded row stride (multiple of 4 for float4 LDS)

// dynamic smem layout for kC (floats): Gs | Ws | QR (F^T then R^T) | vecs
#define OFF_GS   0
#define OFF_WS   4096
#define OFF_QR   8192
#define OFF_KSS  (OFF_QR + 64*QPAD)
#define OFF_B1   (OFF_KSS + 64)
#define OFF_B2   (OFF_B1 + 64)
#define OFF_GM   (OFF_B2 + 64)
#define OFF_BT   (OFF_GM + 64)
#define KC_SMEM_FLOATS (OFF_BT + 64)
#define KC_SMEM_BYTES  (KC_SMEM_FLOATS * 4)   // ~51.5 KB -> 4 blocks/SM

// Scratch (static device allocations; no cudaMalloc allowed)
__device__ float g_S5[BT*5*Dd*Dd];     // partial S = sum_n sc_n f f^T per (bt,chunk)
__device__ float g_ss5[BT*5*Dd];       // partial ss = sum_n sc_n f[n,:]
__device__ float g_G[BW*Dd*Dd];        // per-window diag(sw^2) S_win w1
__device__ float g_v[BW*Dd];           // per-window sw^2 * ss_win

// ---- packed f32x2 helpers (sm_103a) ---------------------------------------
__device__ __forceinline__ unsigned long long pk2(float lo, float hi) {
    unsigned long long r;
    asm("mov.b64 %0, {%1, %2};" : "=l"(r) : "f"(lo), "f"(hi));
    return r;
}
__device__ __forceinline__ void unpk2(unsigned long long v, float& lo, float& hi) {
    asm("mov.b64 {%0, %1}, %2;" : "=f"(lo), "=f"(hi) : "l"(v));
}
__device__ __forceinline__ unsigned long long mul2(unsigned long long a,
                                                   unsigned long long b) {
    unsigned long long r;
    asm("mul.rn.f32x2 %0, %1, %2;" : "=l"(r) : "l"(a), "l"(b));
    return r;
}
__device__ __forceinline__ void fma2(unsigned long long& d,
                                     unsigned long long a,
                                     unsigned long long b) {
    asm("fma.rn.f32x2 %0, %1, %2, %0;" : "+l"(d) : "l"(a), "l"(b));
}

// ---------------------------------------------------------------------------
// Kernel A (frozen): per (bt, chunk of <=64 rows):
//   sc_n = 1/max(||f_n .* sw||,eps); partial S (symmetric, upper-tri 4x4
//   tiles mirrored); partial ss. 256 threads, norm fused into staging.
// ---------------------------------------------------------------------------
__global__ __launch_bounds__(256) void kA(const float* __restrict__ feat,
                                          const float* __restrict__ weights) {
    __shared__ float fs[64][Dd];
    __shared__ float scs[64];
    const int blk = blockIdx.x;
    const int bt  = blk / 5;
    const int c   = blk % 5;
    const int r0  = c * 64;
    const int nr  = min(64, Nn - r0);     // 64 or 44
    const int tid = threadIdx.x;
    const int c4  = tid & 15;             // float4 slot within a row

    float4 swv;
    swv.x = 1.0f / (1.0f + expf(-weights[c4*4 + 0]));
    swv.y = 1.0f / (1.0f + expf(-weights[c4*4 + 1]));
    swv.z = 1.0f / (1.0f + expf(-weights[c4*4 + 2]));
    swv.w = 1.0f / (1.0f + expf(-weights[c4*4 + 3]));

    const float* fbase = feat + ((size_t)bt * Nn + r0) * Dd;
    const int nv   = nr * 16;                 // float4 count
    const int trip = ((nv + 255) & ~255);     // uniform trip count for shfl

    for (int i = tid; i < trip; i += 256) {
        float4 v = make_float4(0.f, 0.f, 0.f, 0.f);
        const bool ok = i < nv;
        if (ok) v = ((const float4*)fbase)[i];
        const float px = v.x*swv.x, py = v.y*swv.y;
        const float pz = v.z*swv.z, pw = v.w*swv.w;
        float ps = px*px + py*py + pz*pz + pw*pw;
        ps += __shfl_xor_sync(0xffffffffu, ps, 1, 16);
        ps += __shfl_xor_sync(0xffffffffu, ps, 2, 16);
        ps += __shfl_xor_sync(0xffffffffu, ps, 4, 16);
        ps += __shfl_xor_sync(0xffffffffu, ps, 8, 16);
        if (ok) {
            ((float4*)fs)[i] = v;
            if (c4 == 0)
                scs[i >> 4] = 1.0f / fmaxf(sqrtf(ps), 1e-12f);
        }
    }
    __syncthreads();

    if (tid < 136) {
        int t = tid, rr = 0;
        while (t >= 16 - rr) { t -= 16 - rr; ++rr; }
        const int cc = rr + t;

        unsigned long long acc2[2][4];
        #pragma unroll
        for (int p = 0; p < 2; ++p)
            #pragma unroll
            for (int d = 0; d < 4; ++d) acc2[p][d] = 0ull;

        #pragma unroll 8
        for (int n = 0; n < nr; ++n) {
            const float  sc = scs[n];
            const float4 w4 = *(const float4*)&fs[n][rr*4];
            const float4 f4 = *(const float4*)&fs[n][cc*4];
            const unsigned long long scp = pk2(sc, sc);
            const unsigned long long sv01 = mul2(scp, pk2(w4.x, w4.y));
            const unsigned long long sv23 = mul2(scp, pk2(w4.z, w4.w));
            const float fv[4] = {f4.x, f4.y, f4.z, f4.w};
            #pragma unroll
            for (int d = 0; d < 4; ++d) {
                const unsigned long long fdd = pk2(fv[d], fv[d]);
                fma2(acc2[0][d], sv01, fdd);
                fma2(acc2[1][d], sv23, fdd);
            }
        }

        float acc[4][4];
        #pragma unroll
        for (int d = 0; d < 4; ++d) {
            unpk2(acc2[0][d], acc[0][d], acc[1][d]);
            unpk2(acc2[1][d], acc[2][d], acc[3][d]);
        }

        float* Sb = g_S5 + (size_t)blk * Dd * Dd;
        #pragma unroll
        for (int jj = 0; jj < 4; ++jj)
            *(float4*)&Sb[(rr*4 + jj)*Dd + cc*4] =
                make_float4(acc[jj][0], acc[jj][1], acc[jj][2], acc[jj][3]);
        if (rr != cc) {
            #pragma unroll
            for (int dd = 0; dd < 4; ++dd)
                *(float4*)&Sb[(cc*4 + dd)*Dd + rr*4] =
                    make_float4(acc[0][dd], acc[1][dd], acc[2][dd], acc[3][dd]);
        }
    } else if (tid >= 224 && tid < 240) {
        const int jg = tid - 224;
        float ksa[4] = {0.f, 0.f, 0.f, 0.f};
        #pragma unroll 4
        for (int n = 0; n < nr; ++n) {
            const float  sc = scs[n];
            const float4 w4 = *(const float4*)&fs[n][jg*4];
            ksa[0] += sc*w4.x; ksa[1] += sc*w4.y;
            ksa[2] += sc*w4.z; ksa[3] += sc*w4.w;
        }
        *(float4*)&g_ss5[blk*Dd + jg*4] =
            make_float4(ksa[0], ksa[1], ksa[2], ksa[3]);
    }
}

// ---------------------------------------------------------------------------
// Kernel B (frozen from R16): per window:
//   Ss = raw symmetric window sum; G = diag(sw2) Ss w1 via column-read
//   symmetry (float4 a-side, 4x4 tiles, f32x2); v = sw2 * ss_win.
// ---------------------------------------------------------------------------
__global__ __launch_bounds__(256) void kB(const float* __restrict__ w1,
                                          const float* __restrict__ weights) {
    __shared__ float Ss[Dd*Dd];      // raw symmetric window sum
    __shared__ float w1s[Dd*Dd];
    __shared__ float sw2[Dd];
    const int bw  = blockIdx.x;
    const int b   = bw / T2;
    const int t2  = bw % T2;
    const int bt0 = b * Tt + t2;
    const int tid = threadIdx.x;

    if (tid < Dd) {
        float s = 1.0f / (1.0f + expf(-weights[tid]));
        sw2[tid] = s * s;
    }
    __syncthreads();

    for (int i = tid; i < 1024; i += 256) {
        float4 m = make_float4(0.f, 0.f, 0.f, 0.f);
        #pragma unroll
        for (int s = 0; s < 3; ++s)
            #pragma unroll
            for (int cc = 0; cc < 5; ++cc) {
                const float4 v = ((const float4*)(g_S5 +
                    (size_t)((bt0 + s)*5 + cc) * Dd * Dd))[i];
                m.x += v.x; m.y += v.y; m.z += v.z; m.w += v.w;
            }
        ((float4*)Ss)[i]  = m;                       // RAW (no sw2 here)
        ((float4*)w1s)[i] = ((const float4*)w1)[i];
    }
    if (tid < Dd) {
        float s = 0.0f;
        #pragma unroll
        for (int sl = 0; sl < 15; ++sl)
            s += g_ss5[((bt0 + sl/5)*5 + sl%5)*Dd + tid];
        g_v[bw*Dd + tid] = sw2[tid] * s;
    }
    __syncthreads();

    const int ty = tid >> 4;
    const int tx = tid & 15;
    float s2v[4];
    #pragma unroll
    for (int i = 0; i < 4; ++i) s2v[i] = sw2[ty*4 + i];

    unsigned long long acc2[4][2];
    #pragma unroll
    for (int i = 0; i < 4; ++i) { acc2[i][0] = 0ull; acc2[i][1] = 0ull; }

    #pragma unroll 8
    for (int k = 0; k < 64; ++k) {
        const float4 a4 = *(const float4*)&Ss[k*Dd + ty*4];
        const float4 b4 = *(const float4*)&w1s[k*Dd + tx*4];
        const unsigned long long b01 = pk2(b4.x, b4.y);
        const unsigned long long b23 = pk2(b4.z, b4.w);
        const float av[4] = {a4.x, a4.y, a4.z, a4.w};
        #pragma unroll
        for (int i = 0; i < 4; ++i) {
            const unsigned long long ad = pk2(av[i], av[i]);
            fma2(acc2[i][0], ad, b01);
            fma2(acc2[i][1], ad, b23);
        }
    }

    float* Gb = g_G + (size_t)bw * Dd * Dd;
    #pragma unroll
    for (int i = 0; i < 4; ++i) {
        float g0, g1, g2, g3;
        unpk2(acc2[i][0], g0, g1);
        unpk2(acc2[i][1], g2, g3);
        *(float4*)&Gb[(ty*4 + i)*Dd + tx*4] =
            make_float4(g0*s2v[i], g1*s2v[i], g2*s2v[i], g3*s2v[i]);
    }
}

// ---------------------------------------------------------------------------
// Kernel C: per (window, 64-row tile). Dynamic smem 51.5KB -> 4 blocks/SM.
// QR holds F^T for GEMM1 then (after barrier) R^T for GEMM2.
// Three barriers; w2 load overlaps GEMM1 via cp.async into Ws.
// ---------------------------------------------------------------------------
__global__ __launch_bounds__(256, 4) void kC(const float* __restrict__ feat,
                                             const float* __restrict__ b1,
                                             const float* __restrict__ w2,
                                             const float* __restrict__ b2,
                                             const float* __restrict__ gamma,
                                             const float* __restrict__ beta,
                                             float* __restrict__ out) {
    extern __shared__ float sm[];
    float* Gs  = sm + OFF_GS;
    float* Ws  = sm + OFF_WS;
    float* QR  = sm + OFF_QR;
    float* kss = sm + OFF_KSS;
    float* b1s = sm + OFF_B1;
    float* b2s = sm + OFF_B2;
    float* gms = sm + OFF_GM;
    float* bts = sm + OFF_BT;

    const int blk  = blockIdx.x;
    const int bw   = blk / 5;
    const int tile = blk % 5;
    const int r0   = tile * 64;
    const int nr   = min(64, Nn - r0);
    const int b    = bw / T2;
    const int t2   = bw % T2;
    const int tid  = threadIdx.x;
    const int ty   = tid >> 4;       // row group 0..15
    const int tx   = tid & 15;       // col group 0..15

    const float* fb = feat + ((size_t)((b*Tt + t2 + 2)*Nn) + r0) * Dd;

    // cp.async: prefetch w2 into Ws (overlaps everything up to GEMM2)
    {
        unsigned int ws_addr = (unsigned int)__cvta_generic_to_shared(Ws);
        #pragma unroll
        for (int i = 0; i < 4; ++i) {
            const unsigned int dst = ws_addr + (tid + i*256) * 16;
            const float4* src = ((const float4*)w2) + tid + i*256;
            asm volatile("cp.async.cg.shared.global [%0], [%1], 16;"
                         :: "r"(dst), "l"(src));
        }
        asm volatile("cp.async.commit_group;");
    }

    // stage F^T (zero-fill invalid rows), G, small vectors
    {
        const float4* qb = (const float4*)fb;
        for (int idx = tid; idx < 1024; idx += 256) {
            const int row = idx >> 4, c4 = idx & 15;
            float4 v = make_float4(0.f, 0.f, 0.f, 0.f);
            if (row < nr) v = qb[row*16 + c4];
            QR[(c4*4 + 0)*QPAD + row] = v.x;
            QR[(c4*4 + 1)*QPAD + row] = v.y;
            QR[(c4*4 + 2)*QPAD + row] = v.z;
            QR[(c4*4 + 3)*QPAD + row] = v.w;
        }
        const float4* Gb = (const float4*)(g_G + (size_t)bw * Dd * Dd);
        for (int i = tid; i < 1024; i += 256)
            ((float4*)Gs)[i] = Gb[i];
        if (tid < Dd) {
            kss[tid] = g_v[bw*Dd + tid];
            b1s[tid] = b1[tid]; b2s[tid] = b2[tid];
            gms[tid] = gamma[tid]; bts[tid] = beta[tid];
        }
    }
    __syncthreads();                 // barrier 1

    // GEMM1: u = F @ G, column-packed; deg = F @ v fused.
    unsigned long long acc2[4][2];
    #pragma unroll
    for (int i = 0; i < 4; ++i) { acc2[i][0] = 0ull; acc2[i][1] = 0ull; }
    float dg[4] = {0.f, 0.f, 0.f, 0.f};

    #pragma unroll 8
    for (int k = 0; k < 64; ++k) {
        const float4 a4 = *(const float4*)&QR[k*QPAD + ty*4];
        const float4 b4 = *(const float4*)&Gs[k*Dd + tx*4];
        const float  vk = kss[k];
        const unsigned long long b01 = pk2(b4.x, b4.y);
        const unsigned long long b23 = pk2(b4.z, b4.w);
        const float av[4] = {a4.x, a4.y, a4.z, a4.w};
        #pragma unroll
        for (int i = 0; i < 4; ++i) {
            const unsigned long long ad = pk2(av[i], av[i]);
            fma2(acc2[i][0], ad, b01);
            fma2(acc2[i][1], ad, b23);
            dg[i] += av[i] * vk;
        }
    }

    float acc[4][4];
    #pragma unroll
    for (int i = 0; i < 4; ++i) {
        unpk2(acc2[i][0], acc[i][0], acc[i][1]);
        unpk2(acc2[i][1], acc[i][2], acc[i][3]);
    }

    // relu(u/deg + b1) -> registers
    #pragma unroll
    for (int i = 0; i < 4; ++i) {
        const float dinv = (dg[i] == 0.0f) ? 0.0f : 1.0f / dg[i];
        #pragma unroll
        for (int j = 0; j < 4; ++j)
            acc[i][j] = fmaxf(acc[i][j] * dinv + b1s[tx*4 + j], 0.0f);
    }
    __syncthreads();                 // barrier 2 (QR reads done everywhere)

    // write R^T into QR space (vectorized columns)
    #pragma unroll
    for (int j = 0; j < 4; ++j)
        *(float4*)&QR[(tx*4 + j)*QPAD + ty*4] =
            make_float4(acc[0][j], acc[1][j], acc[2][j], acc[3][j]);

    asm volatile("cp.async.wait_group 0;" ::: "memory");
    __syncthreads();                 // barrier 3 (R^T ready + Ws visible)

    // GEMM2: h = R @ w2 (column-packed)
    #pragma unroll
    for (int i = 0; i < 4; ++i) { acc2[i][0] = 0ull; acc2[i][1] = 0ull; }

    #pragma unroll 8
    for (int k = 0; k < 64; ++k) {
        const float4 a4 = *(const float4*)&QR[k*QPAD + ty*4];
        const float4 b4 = *(const float4*)&Ws[k*Dd + tx*4];
        const unsigned long long b01 = pk2(b4.x, b4.y);
        const unsigned long long b23 = pk2(b4.z, b4.w);
        const float av[4] = {a4.x, a4.y, a4.z, a4.w};
        #pragma unroll
        for (int i = 0; i < 4; ++i) {
            const unsigned long long ad = pk2(av[i], av[i]);
            fma2(acc2[i][0], ad, b01);
            fma2(acc2[i][1], ad, b23);
        }
    }
    #pragma unroll
    for (int i = 0; i < 4; ++i) {
        unpk2(acc2[i][0], acc[i][0], acc[i][1]);
        unpk2(acc2[i][1], acc[i][2], acc[i][3]);
    }

    // epilogue: residual + bias, LayerNorm per row (16 threads/row)
    float* ob = out + ((size_t)bw * Nn + r0) * Dd;
    #pragma unroll
    for (int i = 0; i < 4; ++i) {
        const int row = ty*4 + i;
        const bool valid = row < nr;
        float4 f4 = make_float4(0.f, 0.f, 0.f, 0.f);
        if (valid) f4 = ((const float4*)fb)[row*16 + tx];
        float h0 = acc[i][0] + f4.x + b2s[tx*4 + 0];
        float h1 = acc[i][1] + f4.y + b2s[tx*4 + 1];
        float h2 = acc[i][2] + f4.z + b2s[tx*4 + 2];
        float h3 = acc[i][3] + f4.w + b2s[tx*4 + 3];

        float s = h0 + h1 + h2 + h3;
        #pragma unroll
        for (int m = 1; m < 16; m <<= 1)
            s += __shfl_xor_sync(0xffffffffu, s, m, 16);
        const float mu = s * (1.0f / 64.0f);

        float a0 = h0 - mu, a1 = h1 - mu, a2 = h2 - mu, a3 = h3 - mu;
        float vs = a0*a0 + a1*a1 + a2*a2 + a3*a3;
        #pragma unroll
        for (int m = 1; m < 16; m <<= 1)
            vs += __shfl_xor_sync(0xffffffffu, vs, m, 16);
        const float rstd = rsqrtf(vs * (1.0f / 64.0f) + 1e-5f);

        if (valid) {
            float4 o;
            o.x = a0 * rstd * gms[tx*4 + 0] + bts[tx*4 + 0];
            o.y = a1 * rstd * gms[tx*4 + 1] + bts[tx*4 + 1];
            o.z = a2 * rstd * gms[tx*4 + 2] + bts[tx*4 + 2];
            o.w = a3 * rstd * gms[tx*4 + 3] + bts[tx*4 + 3];
            ((float4*)ob)[row*16 + tx] = o;
        }
    }
}

extern "C" void kernel_launch(void* const* d_in, const int* in_sizes, int n_in,
                              void* d_out, int out_size) {
    const float* feat    = (const float*)d_in[0];
    const float* weights = (const float*)d_in[1];
    const float* w1      = (const float*)d_in[2];
    const float* b1      = (const float*)d_in[3];
    const float* w2      = (const float*)d_in[4];
    const float* b2      = (const float*)d_in[5];
    const float* gamma   = (const float*)d_in[6];
    const float* beta    = (const float*)d_in[7];
    float* out = (float*)d_out;

    // idempotent, host-side, non-allocating (needed for >48KB dynamic smem)
    cudaFuncSetAttribute(kC, cudaFuncAttributeMaxDynamicSharedMemorySize,
                         KC_SMEM_BYTES);

    kA<<<BT*5, 256>>>(feat, weights);
    kB<<<BW, 256>>>(w1, weights);
    kC<<<BW*5, 256, KC_SMEM_BYTES>>>(feat, b1, w2, b2, gamma, beta, out);
}